// round 1
// baseline (speedup 1.0000x reference)
#include <cuda_runtime.h>
#include <cuda_bf16.h>
#include <math.h>

#define SEQ   2048
#define DIM   1024
#define NH    16
#define HD    64
#define NEXP  8
#define HID   1408
#define VOCAB 32000
#define NL    2

// ---------------- scratch (global __device__, no allocations) ----------------
__device__ float g_h [SEQ*DIM];
__device__ float g_xn[SEQ*DIM];
__device__ float g_q [SEQ*DIM];
__device__ float g_k [SEQ*DIM];
__device__ float g_v [SEQ*DIM];
__device__ float g_o [SEQ*DIM];
__device__ float g_cos[SEQ*(HD/2)];
__device__ float g_sin[SEQ*(HD/2)];
__device__ float g_g [SEQ*HID];
__device__ float g_u [SEQ*HID];
__device__ float g_y [SEQ*2*DIM];
__device__ int   g_cnt[NEXP];
__device__ int   g_sc [NEXP*SEQ];   // token*2 + slot
__device__ float g_wt [NEXP*SEQ];

// ---------------- embedding ----------------
__global__ void embed_kernel(const int* __restrict__ tok,
                             const float* __restrict__ emb,
                             float* __restrict__ h) {
    int t = blockIdx.x;
    int id = tok[t];
    const float* src = emb + (size_t)id * DIM;
    float* dst = h + (size_t)t * DIM;
    for (int i = threadIdx.x; i < DIM; i += blockDim.x) dst[i] = src[i];
}

// ---------------- rope tables ----------------
__global__ void rope_pre_kernel(const int* __restrict__ start_pos,
                                float* __restrict__ cosb, float* __restrict__ sinb) {
    int t = blockIdx.x;
    int i = threadIdx.x;  // 0..31
    float inv = powf(10000.0f, -(2.0f * (float)i) / (float)HD);
    float ang = (float)(*start_pos + t) * inv;
    cosb[t*32 + i] = cosf(ang);
    sinb[t*32 + i] = sinf(ang);
}

__global__ void rope_apply_kernel(float* __restrict__ q, float* __restrict__ k,
                                  const float* __restrict__ cosb,
                                  const float* __restrict__ sinb) {
    int t = blockIdx.x;
    int tid = threadIdx.x;          // 512 = 16 heads * 32 pairs
    int h = tid >> 5, i = tid & 31;
    float c = cosb[t*32 + i], s = sinb[t*32 + i];
    int base = t*DIM + h*HD + 2*i;
    float a = q[base], b = q[base+1];
    q[base]   = a*c - b*s;
    q[base+1] = a*s + b*c;
    a = k[base]; b = k[base+1];
    k[base]   = a*c - b*s;
    k[base+1] = a*s + b*c;
}

// ---------------- rmsnorm ----------------
__global__ void rmsnorm_kernel(const float* __restrict__ x,
                               const float* __restrict__ w,
                               float* __restrict__ y) {
    int t = blockIdx.x;
    __shared__ float red[256];
    const float* xr = x + (size_t)t * DIM;
    float s = 0.f;
    for (int i = threadIdx.x; i < DIM; i += 256) { float v = xr[i]; s += v*v; }
    red[threadIdx.x] = s; __syncthreads();
    for (int off = 128; off; off >>= 1) {
        if (threadIdx.x < off) red[threadIdx.x] += red[threadIdx.x + off];
        __syncthreads();
    }
    float r = rsqrtf(red[0] / (float)DIM + 1e-5f);
    float* yr = y + (size_t)t * DIM;
    for (int i = threadIdx.x; i < DIM; i += 256) yr[i] = xr[i] * r * w[i];
}

// ---------------- generic tiled GEMM (gather-A / scatter-C / residual / dyn-M) ----------------
#define BM 64
#define BN 64
#define BK 16

__global__ void __launch_bounds__(256)
gemm_kernel(const float* __restrict__ A, const float* __restrict__ B,
            float* __restrict__ C, const float* __restrict__ addC,
            int M, int N, int K,
            const int* __restrict__ gatherA,
            const int* __restrict__ scatterC,
            const int* __restrict__ Mdev) {
    if (Mdev) M = *Mdev;
    int rowTile = blockIdx.y * BM;
    if (rowTile >= M) return;
    int colTile = blockIdx.x * BN;

    __shared__ float As[BK][BM + 1];   // padded: conflict-free stores
    __shared__ float Bs[BK][BN];

    int tid = threadIdx.x;
    int tx = tid & 15, ty = tid >> 4;

    float acc[4][4] = {};

    // A loader mapping: each thread loads a float4 along K
    int am = tid >> 2;
    int ak = (tid & 3) * 4;
    int arow = rowTile + am;
    const float* Aptr = nullptr;
    if (arow < M) {
        int r = gatherA ? (gatherA[arow] >> 1) : arow;
        Aptr = A + (size_t)r * K;
    }
    // B loader mapping
    int bk = tid >> 4;
    int bn = (tid & 15) * 4;

    for (int k0 = 0; k0 < K; k0 += BK) {
        float4 av = Aptr ? *(const float4*)(Aptr + k0 + ak)
                         : make_float4(0.f,0.f,0.f,0.f);
        As[ak+0][am] = av.x; As[ak+1][am] = av.y;
        As[ak+2][am] = av.z; As[ak+3][am] = av.w;
        *(float4*)&Bs[bk][bn] = *(const float4*)(B + (size_t)(k0 + bk) * N + colTile + bn);
        __syncthreads();
        #pragma unroll
        for (int k = 0; k < BK; k++) {
            float a0 = As[k][ty*4+0], a1 = As[k][ty*4+1];
            float a2 = As[k][ty*4+2], a3 = As[k][ty*4+3];
            float4 b = *(const float4*)&Bs[k][tx*4];
            acc[0][0] += a0*b.x; acc[0][1] += a0*b.y; acc[0][2] += a0*b.z; acc[0][3] += a0*b.w;
            acc[1][0] += a1*b.x; acc[1][1] += a1*b.y; acc[1][2] += a1*b.z; acc[1][3] += a1*b.w;
            acc[2][0] += a2*b.x; acc[2][1] += a2*b.y; acc[2][2] += a2*b.z; acc[2][3] += a2*b.w;
            acc[3][0] += a3*b.x; acc[3][1] += a3*b.y; acc[3][2] += a3*b.z; acc[3][3] += a3*b.w;
        }
        __syncthreads();
    }

    #pragma unroll
    for (int i = 0; i < 4; i++) {
        int gr = rowTile + ty*4 + i;
        if (gr >= M) continue;
        size_t crow = scatterC ? (size_t)scatterC[gr] : (size_t)gr;
        float* cp = C + crow * N + colTile + tx*4;
        if (addC) {
            const float* ap = addC + crow * N + colTile + tx*4;
            cp[0] = ap[0] + acc[i][0];
            cp[1] = ap[1] + acc[i][1];
            cp[2] = ap[2] + acc[i][2];
            cp[3] = ap[3] + acc[i][3];
        } else {
            float4 v = make_float4(acc[i][0], acc[i][1], acc[i][2], acc[i][3]);
            *(float4*)cp = v;
        }
    }
}

// ---------------- attention (online softmax, per (query,head) block) ----------------
__global__ void __launch_bounds__(128)
attn_kernel(const float* __restrict__ q, const float* __restrict__ k,
            const float* __restrict__ v, float* __restrict__ o) {
    int t = blockIdx.x;
    int h = blockIdx.y;
    int tid = threadIdx.x;     // 128

    __shared__ float qs[HD];
    __shared__ float sm[128];
    __shared__ float accbuf[128][HD + 1];

    if (tid < HD) qs[tid] = q[(size_t)t*DIM + h*HD + tid] * 0.125f;  // 1/sqrt(64)
    __syncthreads();

    float m = -1e30f, l = 0.f;
    float acc[HD];
    #pragma unroll
    for (int d = 0; d < HD; d++) acc[d] = 0.f;

    for (int j = tid; j <= t; j += 128) {
        const float* kr = k + (size_t)j*DIM + h*HD;
        float s = 0.f;
        #pragma unroll
        for (int d = 0; d < HD; d++) s += qs[d] * kr[d];
        const float* vr = v + (size_t)j*DIM + h*HD;
        if (s <= m) {
            float p = __expf(s - m);
            l += p;
            #pragma unroll
            for (int d = 0; d < HD; d++) acc[d] += p * vr[d];
        } else {
            float c = __expf(m - s);
            m = s;
            l = l * c + 1.f;
            #pragma unroll
            for (int d = 0; d < HD; d++) acc[d] = acc[d] * c + vr[d];
        }
    }

    // block combine: max of m
    sm[tid] = m; __syncthreads();
    for (int off = 64; off; off >>= 1) {
        if (tid < off) sm[tid] = fmaxf(sm[tid], sm[tid + off]);
        __syncthreads();
    }
    float M = sm[0]; __syncthreads();
    float c = __expf(m - M);          // 0 for threads with no keys
    sm[tid] = l * c; __syncthreads();
    for (int off = 64; off; off >>= 1) {
        if (tid < off) sm[tid] += sm[tid + off];
        __syncthreads();
    }
    float L = sm[0];
    #pragma unroll
    for (int d = 0; d < HD; d++) accbuf[tid][d] = acc[d] * c;
    __syncthreads();
    if (tid < HD) {
        float s = 0.f;
        for (int i = 0; i < 128; i++) s += accbuf[i][tid];
        o[(size_t)t*DIM + h*HD + tid] = s / L;
    }
}

// ---------------- router: logits, softmax, top2, expert binning ----------------
__global__ void zero_cnt_kernel(int* cnt) { if (threadIdx.x < NEXP) cnt[threadIdx.x] = 0; }

__global__ void router_kernel(const float* __restrict__ x, const float* __restrict__ rw,
                              int* __restrict__ cnt, int* __restrict__ sc,
                              float* __restrict__ wt) {
    int t = blockIdx.x;
    int tid = threadIdx.x;            // 256 = 8 warps
    int w8 = tid >> 5, lane = tid & 31;
    __shared__ float lg[NEXP];
    float s = 0.f;
    const float* xr = x + (size_t)t * DIM;
    for (int kk = lane; kk < DIM; kk += 32) s += xr[kk] * rw[kk*NEXP + w8];
    #pragma unroll
    for (int off = 16; off; off >>= 1) s += __shfl_xor_sync(0xffffffff, s, off);
    if (lane == 0) lg[w8] = s;
    __syncthreads();
    if (tid == 0) {
        float mx = lg[0];
        #pragma unroll
        for (int e = 1; e < NEXP; e++) mx = fmaxf(mx, lg[e]);
        float p[NEXP]; float se = 0.f;
        #pragma unroll
        for (int e = 0; e < NEXP; e++) { p[e] = __expf(lg[e] - mx); se += p[e]; }
        #pragma unroll
        for (int e = 0; e < NEXP; e++) p[e] /= se;
        int i0 = 0;
        #pragma unroll
        for (int e = 1; e < NEXP; e++) if (p[e] > p[i0]) i0 = e;
        int i1 = (i0 == 0) ? 1 : 0;
        #pragma unroll
        for (int e = 0; e < NEXP; e++) if (e != i0 && p[e] > p[i1]) i1 = e;
        int pos = atomicAdd(&cnt[i0], 1);
        sc[i0*SEQ + pos] = t*2 + 0; wt[i0*SEQ + pos] = p[i0];
        pos = atomicAdd(&cnt[i1], 1);
        sc[i1*SEQ + pos] = t*2 + 1; wt[i1*SEQ + pos] = p[i1];
    }
}

// ---------------- silu(g) * u * routing weight ----------------
__global__ void act_kernel(float* __restrict__ g, const float* __restrict__ u,
                           const float* __restrict__ wt, const int* __restrict__ cnt) {
    int i = blockIdx.y;
    if (i >= *cnt) return;
    int j = blockIdx.x * 256 + threadIdx.x;
    if (j >= HID) return;
    float gv = g[(size_t)i*HID + j];
    float sv = gv / (1.f + __expf(-gv));
    g[(size_t)i*HID + j] = sv * u[(size_t)i*HID + j] * wt[i];
}

// ---------------- residual add of the two expert outputs ----------------
__global__ void moe_resid_kernel(float* __restrict__ h, const float* __restrict__ y) {
    int t = blockIdx.y;
    int j = blockIdx.x * 256 + threadIdx.x;
    h[(size_t)t*DIM + j] += y[(size_t)(t*2)*DIM + j] + y[(size_t)(t*2+1)*DIM + j];
}

// ---------------- host orchestration ----------------
static void launch_gemm(const float* A, const float* B, float* C, const float* addC,
                        int M, int N, int K,
                        const int* gatherA, const int* scatterC, const int* Mdev) {
    dim3 grid(N / BN, (M + BM - 1) / BM);
    gemm_kernel<<<grid, 256>>>(A, B, C, addC, M, N, K, gatherA, scatterC, Mdev);
}

extern "C" void kernel_launch(void* const* d_in, const int* in_sizes, int n_in,
                              void* d_out, int out_size) {
    const int*   tokens      = (const int*)  d_in[0];
    const int*   start_pos   = (const int*)  d_in[1];
    const float* tok_emb     = (const float*)d_in[2];
    const float* wq          = (const float*)d_in[3];
    const float* wk          = (const float*)d_in[4];
    const float* wv          = (const float*)d_in[5];
    const float* wo          = (const float*)d_in[6];
    const float* attn_norm_w = (const float*)d_in[7];
    const float* ffn_norm_w  = (const float*)d_in[8];
    const float* router_w    = (const float*)d_in[9];
    const float* w1          = (const float*)d_in[10];
    const float* w2          = (const float*)d_in[11];
    const float* w3          = (const float*)d_in[12];
    const float* final_norm_w= (const float*)d_in[13];
    const float* out_w       = (const float*)d_in[14];
    float*       out         = (float*)d_out;

    float *h, *xn, *q, *k, *v, *o, *cosb, *sinb, *gb, *ub, *yb, *wt;
    int *cnt, *sc;
    cudaGetSymbolAddress((void**)&h,    g_h);
    cudaGetSymbolAddress((void**)&xn,   g_xn);
    cudaGetSymbolAddress((void**)&q,    g_q);
    cudaGetSymbolAddress((void**)&k,    g_k);
    cudaGetSymbolAddress((void**)&v,    g_v);
    cudaGetSymbolAddress((void**)&o,    g_o);
    cudaGetSymbolAddress((void**)&cosb, g_cos);
    cudaGetSymbolAddress((void**)&sinb, g_sin);
    cudaGetSymbolAddress((void**)&gb,   g_g);
    cudaGetSymbolAddress((void**)&ub,   g_u);
    cudaGetSymbolAddress((void**)&yb,   g_y);
    cudaGetSymbolAddress((void**)&wt,   g_wt);
    cudaGetSymbolAddress((void**)&cnt,  g_cnt);
    cudaGetSymbolAddress((void**)&sc,   g_sc);

    embed_kernel<<<SEQ, 256>>>(tokens, tok_emb, h);
    rope_pre_kernel<<<SEQ, 32>>>(start_pos, cosb, sinb);

    for (int l = 0; l < NL; l++) {
        // ---- attention block ----
        rmsnorm_kernel<<<SEQ, 256>>>(h, attn_norm_w + (size_t)l*DIM, xn);
        launch_gemm(xn, wq + (size_t)l*DIM*DIM, q, nullptr, SEQ, DIM, DIM, nullptr, nullptr, nullptr);
        launch_gemm(xn, wk + (size_t)l*DIM*DIM, k, nullptr, SEQ, DIM, DIM, nullptr, nullptr, nullptr);
        launch_gemm(xn, wv + (size_t)l*DIM*DIM, v, nullptr, SEQ, DIM, DIM, nullptr, nullptr, nullptr);
        rope_apply_kernel<<<SEQ, 512>>>(q, k, cosb, sinb);
        attn_kernel<<<dim3(SEQ, NH), 128>>>(q, k, v, o);
        launch_gemm(o, wo + (size_t)l*DIM*DIM, h, h, SEQ, DIM, DIM, nullptr, nullptr, nullptr);

        // ---- MoE block ----
        rmsnorm_kernel<<<SEQ, 256>>>(h, ffn_norm_w + (size_t)l*DIM, xn);
        zero_cnt_kernel<<<1, 32>>>(cnt);
        router_kernel<<<SEQ, 256>>>(xn, router_w + (size_t)l*DIM*NEXP, cnt, sc, wt);
        for (int e = 0; e < NEXP; e++) {
            size_t we = (size_t)(l*NEXP + e);
            const int* idx = sc + (size_t)e*SEQ;
            const int* mc  = cnt + e;
            launch_gemm(xn, w1 + we*DIM*HID, gb, nullptr, SEQ, HID, DIM, idx, nullptr, mc);
            launch_gemm(xn, w3 + we*DIM*HID, ub, nullptr, SEQ, HID, DIM, idx, nullptr, mc);
            act_kernel<<<dim3((HID + 255)/256, SEQ), 256>>>(gb, ub, wt + (size_t)e*SEQ, mc);
            launch_gemm(gb, w2 + we*HID*DIM, yb, nullptr, SEQ, DIM, HID, nullptr, idx, mc);
        }
        moe_resid_kernel<<<dim3(DIM/256, SEQ), 256>>>(h, yb);
    }

    rmsnorm_kernel<<<SEQ, 256>>>(h, final_norm_w, xn);
    launch_gemm(xn, out_w, out, nullptr, SEQ, VOCAB, DIM, nullptr, nullptr, nullptr);

    (void)in_sizes; (void)n_in; (void)out_size;
}

// round 2
// speedup vs baseline: 2.5523x; 2.5523x over previous
#include <cuda_runtime.h>
#include <cuda_bf16.h>
#include <math.h>

#define SEQ   2048
#define DIM   1024
#define NH    16
#define HD    64
#define NEXP  8
#define HID   1408
#define VOCAB 32000
#define NL    2

// ---------------- scratch (global __device__, no allocations) ----------------
__device__ float g_h [SEQ*DIM];
__device__ float g_xn[SEQ*DIM];
__device__ float g_q [SEQ*DIM];
__device__ float g_k [SEQ*DIM];
__device__ float g_v [SEQ*DIM];
__device__ float g_o [SEQ*DIM];
__device__ float g_cos[SEQ*(HD/2)];
__device__ float g_sin[SEQ*(HD/2)];
__device__ float g_g [SEQ*HID];
__device__ float g_u [SEQ*HID];
__device__ float g_y [SEQ*2*DIM];
__device__ int   g_cnt[NEXP];
__device__ int   g_sc [NEXP*SEQ];   // token*2 + slot
__device__ float g_wt [NEXP*SEQ];

// ---------------- embedding ----------------
__global__ void embed_kernel(const int* __restrict__ tok,
                             const float* __restrict__ emb,
                             float* __restrict__ h) {
    int t = blockIdx.x;
    int id = tok[t];
    const float* src = emb + (size_t)id * DIM;
    float* dst = h + (size_t)t * DIM;
    for (int i = threadIdx.x; i < DIM; i += blockDim.x) dst[i] = src[i];
}

// ---------------- rope tables ----------------
__global__ void rope_pre_kernel(const int* __restrict__ start_pos,
                                float* __restrict__ cosb, float* __restrict__ sinb) {
    int t = blockIdx.x;
    int i = threadIdx.x;  // 0..31
    float inv = powf(10000.0f, -(2.0f * (float)i) / (float)HD);
    float ang = (float)(*start_pos + t) * inv;
    cosb[t*32 + i] = cosf(ang);
    sinb[t*32 + i] = sinf(ang);
}

__global__ void rope_apply_kernel(float* __restrict__ q, float* __restrict__ k,
                                  const float* __restrict__ cosb,
                                  const float* __restrict__ sinb) {
    int t = blockIdx.x;
    int tid = threadIdx.x;          // 512 = 16 heads * 32 pairs
    int h = tid >> 5, i = tid & 31;
    float c = cosb[t*32 + i], s = sinb[t*32 + i];
    int base = t*DIM + h*HD + 2*i;
    float a = q[base], b = q[base+1];
    q[base]   = a*c - b*s;
    q[base+1] = a*s + b*c;
    a = k[base]; b = k[base+1];
    k[base]   = a*c - b*s;
    k[base+1] = a*s + b*c;
}

// ---------------- rmsnorm ----------------
__global__ void rmsnorm_kernel(const float* __restrict__ x,
                               const float* __restrict__ w,
                               float* __restrict__ y) {
    int t = blockIdx.x;
    __shared__ float red[256];
    const float* xr = x + (size_t)t * DIM;
    float s = 0.f;
    for (int i = threadIdx.x; i < DIM; i += 256) { float v = xr[i]; s += v*v; }
    red[threadIdx.x] = s; __syncthreads();
    for (int off = 128; off; off >>= 1) {
        if (threadIdx.x < off) red[threadIdx.x] += red[threadIdx.x + off];
        __syncthreads();
    }
    float r = rsqrtf(red[0] / (float)DIM + 1e-5f);
    float* yr = y + (size_t)t * DIM;
    for (int i = threadIdx.x; i < 256; i += 256) {}
    for (int i = threadIdx.x; i < DIM; i += 256) yr[i] = xr[i] * r * w[i];
}

// ---------------- fp32 GEMM: 128x128 tile, 8x8 micro, double-buffered ----------------
#define GBM 128
#define GBN 128
#define GBK 8

__global__ void __launch_bounds__(256)
gemm_kernel(const float* __restrict__ A, const float* __restrict__ B,
            float* __restrict__ C, const float* __restrict__ addC,
            int M, int N, int K,
            const int* __restrict__ gatherA,
            const int* __restrict__ scatterC,
            const int* __restrict__ Mdev) {
    if (Mdev) M = *Mdev;
    int rowTile = blockIdx.y * GBM;
    if (rowTile >= M) return;
    int colTile = blockIdx.x * GBN;

    __shared__ float As[2][GBK][GBM + 4];
    __shared__ float Bs[2][GBK][GBN];

    int tid = threadIdx.x;

    // A loader: each thread loads one float4 along K. row = tid>>1, k off = (tid&1)*4
    int lrow = tid >> 1;
    int lk   = (tid & 1) * 4;
    int garow = rowTile + lrow;
    const float* Aptr = nullptr;
    if (garow < M) {
        int r = gatherA ? (gatherA[garow] >> 1) : garow;
        Aptr = A + (size_t)r * K;
    }
    // B loader: bk = tid>>5 (0..7), bn = (tid&31)*4
    int bk = tid >> 5;
    int bn = (tid & 31) * 4;
    const float* Bptr = B + (size_t)bk * N + colTile + bn;

    int tx = tid & 15, ty = tid >> 4;

    float acc[8][8];
    #pragma unroll
    for (int i = 0; i < 8; i++)
        #pragma unroll
        for (int j = 0; j < 8; j++) acc[i][j] = 0.f;

    float4 aF, bF;
    // prologue fetch k0=0
    aF = Aptr ? *(const float4*)(Aptr + lk) : make_float4(0.f,0.f,0.f,0.f);
    bF = *(const float4*)Bptr;
    As[0][lk+0][lrow] = aF.x; As[0][lk+1][lrow] = aF.y;
    As[0][lk+2][lrow] = aF.z; As[0][lk+3][lrow] = aF.w;
    *(float4*)&Bs[0][bk][bn] = bF;
    __syncthreads();

    int buf = 0;
    for (int k0 = 0; k0 < K; k0 += GBK) {
        bool more = (k0 + GBK) < K;
        if (more) {
            aF = Aptr ? *(const float4*)(Aptr + k0 + GBK + lk) : make_float4(0.f,0.f,0.f,0.f);
            bF = *(const float4*)(Bptr + (size_t)(k0 + GBK) * N);
        }
        #pragma unroll
        for (int k = 0; k < GBK; k++) {
            float a[8], b[8];
            *(float4*)&a[0] = *(const float4*)&As[buf][k][ty*4];
            *(float4*)&a[4] = *(const float4*)&As[buf][k][64 + ty*4];
            *(float4*)&b[0] = *(const float4*)&Bs[buf][k][tx*4];
            *(float4*)&b[4] = *(const float4*)&Bs[buf][k][64 + tx*4];
            #pragma unroll
            for (int i = 0; i < 8; i++)
                #pragma unroll
                for (int j = 0; j < 8; j++)
                    acc[i][j] += a[i] * b[j];
        }
        if (more) {
            int nb = buf ^ 1;
            As[nb][lk+0][lrow] = aF.x; As[nb][lk+1][lrow] = aF.y;
            As[nb][lk+2][lrow] = aF.z; As[nb][lk+3][lrow] = aF.w;
            *(float4*)&Bs[nb][bk][bn] = bF;
        }
        __syncthreads();
        buf ^= 1;
    }

    // epilogue: rows {ty*4+i, 64+ty*4+i}, cols {tx*4+j, 64+tx*4+j}
    #pragma unroll
    for (int ih = 0; ih < 2; ih++) {
        #pragma unroll
        for (int i = 0; i < 4; i++) {
            int gr = rowTile + ih*64 + ty*4 + i;
            if (gr >= M) continue;
            size_t crow = scatterC ? (size_t)scatterC[gr] : (size_t)gr;
            #pragma unroll
            for (int jh = 0; jh < 2; jh++) {
                float* cp = C + crow * N + colTile + jh*64 + tx*4;
                float4 vv = make_float4(acc[ih*4+i][jh*4+0], acc[ih*4+i][jh*4+1],
                                        acc[ih*4+i][jh*4+2], acc[ih*4+i][jh*4+3]);
                if (addC) {
                    const float* ap = addC + crow * N + colTile + jh*64 + tx*4;
                    vv.x += ap[0]; vv.y += ap[1]; vv.z += ap[2]; vv.w += ap[3];
                }
                *(float4*)cp = vv;
            }
        }
    }
}

// ---------------- attention: flash-style tiles (64 q x 32 k), 256 threads ----------------
#define AQ 64
#define AK 32

__global__ void __launch_bounds__(256)
attn_kernel(const float* __restrict__ q, const float* __restrict__ k,
            const float* __restrict__ v, float* __restrict__ o) {
    int qt0 = blockIdx.x * AQ;
    int h   = blockIdx.y;
    int tid = threadIdx.x;
    int tx  = tid & 7;    // key group (4 keys) / O col group
    int ty  = tid >> 3;   // 0..31 -> q rows ty*2, ty*2+1

    __shared__ float Qs[HD][AQ + 4];   // [d][r]
    __shared__ float Ks[HD][AK + 4];   // [d][j]
    __shared__ float Vs[AK][HD + 4];   // [j][c]
    __shared__ float Ps[AK][AQ + 4];   // [j][r]

    // load Q tile (scaled)
    for (int f = tid; f < AQ * (HD/4); f += 256) {
        int r  = f >> 4;
        int dq = (f & 15) * 4;
        float4 qv = *(const float4*)(q + (size_t)(qt0 + r)*DIM + h*HD + dq);
        Qs[dq+0][r] = qv.x * 0.125f;
        Qs[dq+1][r] = qv.y * 0.125f;
        Qs[dq+2][r] = qv.z * 0.125f;
        Qs[dq+3][r] = qv.w * 0.125f;
    }

    float m[2] = {-1e30f, -1e30f};
    float l[2] = {0.f, 0.f};
    float acc[2][8];
    #pragma unroll
    for (int i = 0; i < 2; i++)
        #pragma unroll
        for (int c = 0; c < 8; c++) acc[i][c] = 0.f;

    int qg0 = qt0 + ty*2;
    for (int j0 = 0; j0 <= qt0 + AQ - AK; j0 += AK) {
        __syncthreads();   // previous Ps/Vs consumers done
        // load K (transposed) and V tiles
        for (int f = tid; f < AK * (HD/4); f += 256) {
            int j  = f >> 4;
            int dq = (f & 15) * 4;
            float4 kv = *(const float4*)(k + (size_t)(j0 + j)*DIM + h*HD + dq);
            Ks[dq+0][j] = kv.x; Ks[dq+1][j] = kv.y;
            Ks[dq+2][j] = kv.z; Ks[dq+3][j] = kv.w;
            *(float4*)&Vs[j][dq] = *(const float4*)(v + (size_t)(j0 + j)*DIM + h*HD + dq);
        }
        __syncthreads();

        // S = Q.K^T : [2 rows][4 keys]
        float s[2][4];
        #pragma unroll
        for (int i = 0; i < 2; i++)
            #pragma unroll
            for (int jj = 0; jj < 4; jj++) s[i][jj] = 0.f;
        #pragma unroll 8
        for (int d = 0; d < HD; d++) {
            float a0 = Qs[d][ty*2 + 0];
            float a1 = Qs[d][ty*2 + 1];
            float4 b4 = *(const float4*)&Ks[d][tx*4];
            s[0][0] += a0*b4.x; s[0][1] += a0*b4.y; s[0][2] += a0*b4.z; s[0][3] += a0*b4.w;
            s[1][0] += a1*b4.x; s[1][1] += a1*b4.y; s[1][2] += a1*b4.z; s[1][3] += a1*b4.w;
        }
        // causal mask
        #pragma unroll
        for (int i = 0; i < 2; i++) {
            int qg = qg0 + i;
            #pragma unroll
            for (int jj = 0; jj < 4; jj++)
                if (j0 + tx*4 + jj > qg) s[i][jj] = -1e30f;
        }
        // online softmax stats per row (reduce across tx = lane bits 0..2)
        #pragma unroll
        for (int i = 0; i < 2; i++) {
            float mx = fmaxf(fmaxf(s[i][0], s[i][1]), fmaxf(s[i][2], s[i][3]));
            mx = fmaxf(mx, __shfl_xor_sync(0xffffffff, mx, 1));
            mx = fmaxf(mx, __shfl_xor_sync(0xffffffff, mx, 2));
            mx = fmaxf(mx, __shfl_xor_sync(0xffffffff, mx, 4));
            float mn = fmaxf(m[i], mx);
            float sc = __expf(m[i] - mn);
            float p0 = __expf(s[i][0] - mn);
            float p1 = __expf(s[i][1] - mn);
            float p2 = __expf(s[i][2] - mn);
            float p3 = __expf(s[i][3] - mn);
            float rs = p0 + p1 + p2 + p3;
            rs += __shfl_xor_sync(0xffffffff, rs, 1);
            rs += __shfl_xor_sync(0xffffffff, rs, 2);
            rs += __shfl_xor_sync(0xffffffff, rs, 4);
            l[i] = l[i] * sc + rs;
            m[i] = mn;
            #pragma unroll
            for (int c = 0; c < 8; c++) acc[i][c] *= sc;
            Ps[tx*4+0][ty*2+i] = p0;
            Ps[tx*4+1][ty*2+i] = p1;
            Ps[tx*4+2][ty*2+i] = p2;
            Ps[tx*4+3][ty*2+i] = p3;
        }
        __syncthreads();

        // O += P.V : cols {tx*4..+3, 32+tx*4..+3}
        #pragma unroll 4
        for (int j = 0; j < AK; j++) {
            float p0 = Ps[j][ty*2 + 0];
            float p1 = Ps[j][ty*2 + 1];
            float4 v0 = *(const float4*)&Vs[j][tx*4];
            float4 v1 = *(const float4*)&Vs[j][32 + tx*4];
            acc[0][0] += p0*v0.x; acc[0][1] += p0*v0.y; acc[0][2] += p0*v0.z; acc[0][3] += p0*v0.w;
            acc[0][4] += p0*v1.x; acc[0][5] += p0*v1.y; acc[0][6] += p0*v1.z; acc[0][7] += p0*v1.w;
            acc[1][0] += p1*v0.x; acc[1][1] += p1*v0.y; acc[1][2] += p1*v0.z; acc[1][3] += p1*v0.w;
            acc[1][4] += p1*v1.x; acc[1][5] += p1*v1.y; acc[1][6] += p1*v1.z; acc[1][7] += p1*v1.w;
        }
    }

    // epilogue
    #pragma unroll
    for (int i = 0; i < 2; i++) {
        float inv = 1.f / l[i];
        float* op = o + (size_t)(qg0 + i)*DIM + h*HD;
        float4 o0 = make_float4(acc[i][0]*inv, acc[i][1]*inv, acc[i][2]*inv, acc[i][3]*inv);
        float4 o1 = make_float4(acc[i][4]*inv, acc[i][5]*inv, acc[i][6]*inv, acc[i][7]*inv);
        *(float4*)(op + tx*4)      = o0;
        *(float4*)(op + 32 + tx*4) = o1;
    }
}

// ---------------- router: logits, softmax, top2, expert binning ----------------
__global__ void zero_cnt_kernel(int* cnt) { if (threadIdx.x < NEXP) cnt[threadIdx.x] = 0; }

__global__ void router_kernel(const float* __restrict__ x, const float* __restrict__ rw,
                              int* __restrict__ cnt, int* __restrict__ sc,
                              float* __restrict__ wt) {
    int t = blockIdx.x;
    int tid = threadIdx.x;            // 256 = 8 warps
    int w8 = tid >> 5, lane = tid & 31;
    __shared__ float lg[NEXP];
    float s = 0.f;
    const float* xr = x + (size_t)t * DIM;
    for (int kk = lane; kk < DIM; kk += 32) s += xr[kk] * rw[kk*NEXP + w8];
    #pragma unroll
    for (int off = 16; off; off >>= 1) s += __shfl_xor_sync(0xffffffff, s, off);
    if (lane == 0) lg[w8] = s;
    __syncthreads();
    if (tid == 0) {
        float mx = lg[0];
        #pragma unroll
        for (int e = 1; e < NEXP; e++) mx = fmaxf(mx, lg[e]);
        float p[NEXP]; float se = 0.f;
        #pragma unroll
        for (int e = 0; e < NEXP; e++) { p[e] = __expf(lg[e] - mx); se += p[e]; }
        #pragma unroll
        for (int e = 0; e < NEXP; e++) p[e] /= se;
        int i0 = 0;
        #pragma unroll
        for (int e = 1; e < NEXP; e++) if (p[e] > p[i0]) i0 = e;
        int i1 = (i0 == 0) ? 1 : 0;
        #pragma unroll
        for (int e = 0; e < NEXP; e++) if (e != i0 && p[e] > p[i1]) i1 = e;
        int pos = atomicAdd(&cnt[i0], 1);
        sc[i0*SEQ + pos] = t*2 + 0; wt[i0*SEQ + pos] = p[i0];
        pos = atomicAdd(&cnt[i1], 1);
        sc[i1*SEQ + pos] = t*2 + 1; wt[i1*SEQ + pos] = p[i1];
    }
}

// ---------------- silu(g) * u * routing weight ----------------
__global__ void act_kernel(float* __restrict__ g, const float* __restrict__ u,
                           const float* __restrict__ wt, const int* __restrict__ cnt) {
    int i = blockIdx.y;
    if (i >= *cnt) return;
    int j = blockIdx.x * 256 + threadIdx.x;
    if (j >= HID) return;
    float gv = g[(size_t)i*HID + j];
    float sv = gv / (1.f + __expf(-gv));
    g[(size_t)i*HID + j] = sv * u[(size_t)i*HID + j] * wt[i];
}

// ---------------- residual add of the two expert outputs ----------------
__global__ void moe_resid_kernel(float* __restrict__ h, const float* __restrict__ y) {
    int t = blockIdx.y;
    int j = blockIdx.x * 256 + threadIdx.x;
    h[(size_t)t*DIM + j] += y[(size_t)(t*2)*DIM + j] + y[(size_t)(t*2+1)*DIM + j];
}

// ---------------- host orchestration ----------------
static void launch_gemm(const float* A, const float* B, float* C, const float* addC,
                        int M, int N, int K,
                        const int* gatherA, const int* scatterC, const int* Mdev) {
    dim3 grid(N / GBN, (M + GBM - 1) / GBM);
    gemm_kernel<<<grid, 256>>>(A, B, C, addC, M, N, K, gatherA, scatterC, Mdev);
}

extern "C" void kernel_launch(void* const* d_in, const int* in_sizes, int n_in,
                              void* d_out, int out_size) {
    const int*   tokens      = (const int*)  d_in[0];
    const int*   start_pos   = (const int*)  d_in[1];
    const float* tok_emb     = (const float*)d_in[2];
    const float* wq          = (const float*)d_in[3];
    const float* wk          = (const float*)d_in[4];
    const float* wv          = (const float*)d_in[5];
    const float* wo          = (const float*)d_in[6];
    const float* attn_norm_w = (const float*)d_in[7];
    const float* ffn_norm_w  = (const float*)d_in[8];
    const float* router_w    = (const float*)d_in[9];
    const float* w1          = (const float*)d_in[10];
    const float* w2          = (const float*)d_in[11];
    const float* w3          = (const float*)d_in[12];
    const float* final_norm_w= (const float*)d_in[13];
    const float* out_w       = (const float*)d_in[14];
    float*       out         = (float*)d_out;

    float *h, *xn, *q, *k, *v, *o, *cosb, *sinb, *gb, *ub, *yb, *wt;
    int *cnt, *sc;
    cudaGetSymbolAddress((void**)&h,    g_h);
    cudaGetSymbolAddress((void**)&xn,   g_xn);
    cudaGetSymbolAddress((void**)&q,    g_q);
    cudaGetSymbolAddress((void**)&k,    g_k);
    cudaGetSymbolAddress((void**)&v,    g_v);
    cudaGetSymbolAddress((void**)&o,    g_o);
    cudaGetSymbolAddress((void**)&cosb, g_cos);
    cudaGetSymbolAddress((void**)&sinb, g_sin);
    cudaGetSymbolAddress((void**)&gb,   g_g);
    cudaGetSymbolAddress((void**)&ub,   g_u);
    cudaGetSymbolAddress((void**)&yb,   g_y);
    cudaGetSymbolAddress((void**)&wt,   g_wt);
    cudaGetSymbolAddress((void**)&cnt,  g_cnt);
    cudaGetSymbolAddress((void**)&sc,   g_sc);

    embed_kernel<<<SEQ, 256>>>(tokens, tok_emb, h);
    rope_pre_kernel<<<SEQ, 32>>>(start_pos, cosb, sinb);

    for (int l = 0; l < NL; l++) {
        // ---- attention block ----
        rmsnorm_kernel<<<SEQ, 256>>>(h, attn_norm_w + (size_t)l*DIM, xn);
        launch_gemm(xn, wq + (size_t)l*DIM*DIM, q, nullptr, SEQ, DIM, DIM, nullptr, nullptr, nullptr);
        launch_gemm(xn, wk + (size_t)l*DIM*DIM, k, nullptr, SEQ, DIM, DIM, nullptr, nullptr, nullptr);
        launch_gemm(xn, wv + (size_t)l*DIM*DIM, v, nullptr, SEQ, DIM, DIM, nullptr, nullptr, nullptr);
        rope_apply_kernel<<<SEQ, 512>>>(q, k, cosb, sinb);
        attn_kernel<<<dim3(SEQ/AQ, NH), 256>>>(q, k, v, o);
        launch_gemm(o, wo + (size_t)l*DIM*DIM, h, h, SEQ, DIM, DIM, nullptr, nullptr, nullptr);

        // ---- MoE block ----
        rmsnorm_kernel<<<SEQ, 256>>>(h, ffn_norm_w + (size_t)l*DIM, xn);
        zero_cnt_kernel<<<1, 32>>>(cnt);
        router_kernel<<<SEQ, 256>>>(xn, router_w + (size_t)l*DIM*NEXP, cnt, sc, wt);
        for (int e = 0; e < NEXP; e++) {
            size_t we = (size_t)(l*NEXP + e);
            const int* idx = sc + (size_t)e*SEQ;
            const int* mc  = cnt + e;
            launch_gemm(xn, w1 + we*DIM*HID, gb, nullptr, SEQ, HID, DIM, idx, nullptr, mc);
            launch_gemm(xn, w3 + we*DIM*HID, ub, nullptr, SEQ, HID, DIM, idx, nullptr, mc);
            act_kernel<<<dim3((HID + 255)/256, SEQ), 256>>>(gb, ub, wt + (size_t)e*SEQ, mc);
            launch_gemm(gb, w2 + we*HID*DIM, yb, nullptr, SEQ, DIM, HID, nullptr, idx, mc);
        }
        moe_resid_kernel<<<dim3(DIM/256, SEQ), 256>>>(h, yb);
    }

    rmsnorm_kernel<<<SEQ, 256>>>(h, final_norm_w, xn);
    launch_gemm(xn, out_w, out, nullptr, SEQ, VOCAB, DIM, nullptr, nullptr, nullptr);

    (void)in_sizes; (void)n_in; (void)out_size;
}

// round 4
// speedup vs baseline: 9.4155x; 3.6891x over previous
#include <cuda_runtime.h>
#include <cuda_bf16.h>
#include <math.h>
#include <stdint.h>

#define SEQ   2048
#define DIM   1024
#define NH    16
#define HD    64
#define NEXP  8
#define HID   1408
#define VOCAB 32000
#define NL    2
#define QKVS  (3*DIM)

// ---------------- scratch ----------------
__device__ float g_h  [SEQ*DIM];
__device__ float g_xn [SEQ*DIM];
__device__ float g_qkv[SEQ*QKVS];
__device__ float g_o  [SEQ*DIM];
__device__ float g_cos[SEQ*(HD/2)];
__device__ float g_sin[SEQ*(HD/2)];
__device__ float g_g  [2*SEQ*HID];
__device__ float g_u  [2*SEQ*HID];
__device__ float g_y  [2*SEQ*DIM];
__device__ int   g_cnt[NEXP];
__device__ int   g_off[NEXP+1];
__device__ int   g_sc [NEXP*SEQ];
__device__ float g_wt [NEXP*SEQ];
__device__ int   g_scf[2*SEQ];
__device__ float g_wtf[2*SEQ];

// ---------------- embedding ----------------
__global__ void embed_kernel(const int* __restrict__ tok,
                             const float* __restrict__ emb,
                             float* __restrict__ h) {
    int t = blockIdx.x;
    int id = tok[t];
    const float* src = emb + (size_t)id * DIM;
    float* dst = h + (size_t)t * DIM;
    for (int i = threadIdx.x; i < DIM; i += blockDim.x) dst[i] = src[i];
}

// ---------------- rope ----------------
__global__ void rope_pre_kernel(const int* __restrict__ start_pos,
                                float* __restrict__ cosb, float* __restrict__ sinb) {
    int t = blockIdx.x;
    int i = threadIdx.x;
    float inv = powf(10000.0f, -(2.0f * (float)i) / (float)HD);
    float ang = (float)(*start_pos + t) * inv;
    cosb[t*32 + i] = cosf(ang);
    sinb[t*32 + i] = sinf(ang);
}

__global__ void rope_apply_kernel(float* __restrict__ qkv,
                                  const float* __restrict__ cosb,
                                  const float* __restrict__ sinb) {
    int t = blockIdx.x;
    int tid = threadIdx.x;          // 512 = 16 heads * 32 pairs
    int h = tid >> 5, i = tid & 31;
    float c = cosb[t*32 + i], s = sinb[t*32 + i];
    size_t base = (size_t)t*QKVS + h*HD + 2*i;
    float a = qkv[base], b = qkv[base+1];
    qkv[base]   = a*c - b*s;
    qkv[base+1] = a*s + b*c;
    a = qkv[base+DIM]; b = qkv[base+DIM+1];
    qkv[base+DIM]   = a*c - b*s;
    qkv[base+DIM+1] = a*s + b*c;
}

// ---------------- rmsnorm ----------------
__global__ void rmsnorm_kernel(const float* __restrict__ x,
                               const float* __restrict__ w,
                               float* __restrict__ y) {
    int t = blockIdx.x;
    __shared__ float red[256];
    const float* xr = x + (size_t)t * DIM;
    float s = 0.f;
    for (int i = threadIdx.x; i < DIM; i += 256) { float v = xr[i]; s += v*v; }
    red[threadIdx.x] = s; __syncthreads();
    for (int off = 128; off; off >>= 1) {
        if (threadIdx.x < off) red[threadIdx.x] += red[threadIdx.x + off];
        __syncthreads();
    }
    float r = rsqrtf(red[0] / (float)DIM + 1e-5f);
    float* yr = y + (size_t)t * DIM;
    for (int i = threadIdx.x; i < DIM; i += 256) yr[i] = xr[i] * r * w[i];
}

// ---------------- bf16x3 error-compensated tensor-core GEMM ----------------
#define GBM 128
#define GBN 128
#define GBK 16
#define K2N 8     // GBK/2 packed k-pairs
#define LDP 136   // uint32 row stride: bank = 8*tig + idx -> conflict-free

__device__ __forceinline__ void split_pack(float x, float y, uint32_t& hi, uint32_t& lo) {
    __nv_bfloat16 xh = __float2bfloat16(x);
    __nv_bfloat16 yh = __float2bfloat16(y);
    __nv_bfloat16 xl = __float2bfloat16(x - __bfloat162float(xh));
    __nv_bfloat16 yl = __float2bfloat16(y - __bfloat162float(yh));
    __nv_bfloat162 h2 = __halves2bfloat162(xh, yh);   // x -> low 16 bits
    __nv_bfloat162 l2 = __halves2bfloat162(xl, yl);
    hi = *reinterpret_cast<uint32_t*>(&h2);
    lo = *reinterpret_cast<uint32_t*>(&l2);
}

__device__ __forceinline__ void mma16(float* d, const uint32_t* a, const uint32_t* b) {
    asm volatile("mma.sync.aligned.m16n8k16.row.col.f32.bf16.bf16.f32 "
        "{%0,%1,%2,%3}, {%4,%5,%6,%7}, {%8,%9}, {%0,%1,%2,%3};\n"
        : "+f"(d[0]), "+f"(d[1]), "+f"(d[2]), "+f"(d[3])
        : "r"(a[0]), "r"(a[1]), "r"(a[2]), "r"(a[3]), "r"(b[0]), "r"(b[1]));
}

// Modes:
//  simple: gridDim.z=1, strideB=0, cnt=off=gather=scatter=null
//  QKV:    gridDim.z=3, strideB=0, B0/B1/B2 + C0/C1/C2 selected by z
//  MoE:    gridDim.z=NEXP, strideB!=0 (B=B0+z*strideB, C=C0), cnt/off/gather/scatter
__global__ void __launch_bounds__(256)
gemm_bf16x3(const float* __restrict__ A,
            const float* __restrict__ B0, const float* __restrict__ B1,
            const float* __restrict__ B2, size_t strideB,
            float* __restrict__ C0, float* __restrict__ C1, float* __restrict__ C2,
            const float* __restrict__ addC,
            int M, int N, int K, int ldc,
            const int* __restrict__ gather, const int* __restrict__ scatter,
            const int* __restrict__ cnt, const int* __restrict__ off)
{
    int z = blockIdx.z;
    const float* B;
    float* C;
    if (strideB) { B = B0 + (size_t)z * strideB; C = C0; }
    else         { B = (z==0) ? B0 : (z==1 ? B1 : B2);
                   C = (z==0) ? C0 : (z==1 ? C1 : C2); }
    int Meff = cnt ? cnt[z] : M;
    int base = off ? off[z] : 0;
    int rowTile = blockIdx.y * GBM;
    if (rowTile >= Meff) return;
    int colTile = blockIdx.x * GBN;

    __shared__ uint32_t AsH[2][K2N][LDP];
    __shared__ uint32_t AsL[2][K2N][LDP];
    __shared__ uint32_t BsH[2][K2N][LDP];
    __shared__ uint32_t BsL[2][K2N][LDP];

    int tid  = threadIdx.x;
    int lane = tid & 31;
    int warp = tid >> 5;
    int g    = lane >> 2;
    int tig  = lane & 3;
    int wm = (warp >> 2) * 64;
    int wn = (warp & 3)  * 32;

    // A loader: row = tid>>1, k offset = (tid&1)*8 (8 floats = 4 pairs)
    int lrow = tid >> 1;
    int lk8  = (tid & 1) * 8;
    int k2b  = lk8 >> 1;
    int rl = rowTile + lrow;
    const float* Aptr = nullptr;
    if (rl < Meff) {
        int r = gather ? (gather[z*SEQ + rl] >> 1) : (base + rl);
        Aptr = A + (size_t)r * K;
    }
    // B loader: k-pair = tid>>5 (0..7), n = (tid&31)*4
    int bk2 = tid >> 5;
    int bn  = (tid & 31) * 4;
    const float* Bptr = B + (size_t)(2*bk2) * N + colTile + bn;

    float acc[16][4];
    #pragma unroll
    for (int i = 0; i < 16; i++) { acc[i][0]=acc[i][1]=acc[i][2]=acc[i][3]=0.f; }

    float4 fa0, fa1, fb0, fb1;

    #define FETCH(k0) do { \
        if (Aptr) { fa0 = *(const float4*)(Aptr + (k0) + lk8); \
                    fa1 = *(const float4*)(Aptr + (k0) + lk8 + 4); } \
        else { fa0 = make_float4(0.f,0.f,0.f,0.f); fa1 = fa0; } \
        fb0 = *(const float4*)(Bptr + (size_t)(k0) * N); \
        fb1 = *(const float4*)(Bptr + (size_t)(k0) * N + N); } while(0)

    #define STORE(bf) do { \
        uint32_t h_, l_; \
        split_pack(fa0.x, fa0.y, h_, l_); AsH[bf][k2b+0][lrow] = h_; AsL[bf][k2b+0][lrow] = l_; \
        split_pack(fa0.z, fa0.w, h_, l_); AsH[bf][k2b+1][lrow] = h_; AsL[bf][k2b+1][lrow] = l_; \
        split_pack(fa1.x, fa1.y, h_, l_); AsH[bf][k2b+2][lrow] = h_; AsL[bf][k2b+2][lrow] = l_; \
        split_pack(fa1.z, fa1.w, h_, l_); AsH[bf][k2b+3][lrow] = h_; AsL[bf][k2b+3][lrow] = l_; \
        uint32_t ph[4], pl[4]; \
        split_pack(fb0.x, fb1.x, ph[0], pl[0]); \
        split_pack(fb0.y, fb1.y, ph[1], pl[1]); \
        split_pack(fb0.z, fb1.z, ph[2], pl[2]); \
        split_pack(fb0.w, fb1.w, ph[3], pl[3]); \
        *(uint4*)&BsH[bf][bk2][bn] = *(uint4*)ph; \
        *(uint4*)&BsL[bf][bk2][bn] = *(uint4*)pl; } while(0)

    FETCH(0); STORE(0); __syncthreads();

    int buf = 0;
    for (int k0 = 0; k0 < K; k0 += GBK) {
        bool more = (k0 + GBK) < K;
        if (more) FETCH(k0 + GBK);

        uint32_t ah[4][4], bfh[4][2], bt[4][2];
        #pragma unroll
        for (int mt = 0; mt < 4; mt++) {
            int r0 = wm + mt*16 + g;
            ah[mt][0] = AsH[buf][tig  ][r0];
            ah[mt][1] = AsH[buf][tig  ][r0+8];
            ah[mt][2] = AsH[buf][tig+4][r0];
            ah[mt][3] = AsH[buf][tig+4][r0+8];
        }
        #pragma unroll
        for (int nt = 0; nt < 4; nt++) {
            int c0 = wn + nt*8 + g;
            bfh[nt][0] = BsH[buf][tig  ][c0];
            bfh[nt][1] = BsH[buf][tig+4][c0];
        }
        // pass 1: Ah * Bh
        #pragma unroll
        for (int mt = 0; mt < 4; mt++)
            #pragma unroll
            for (int nt = 0; nt < 4; nt++)
                mma16(acc[mt*4+nt], ah[mt], bfh[nt]);
        // pass 2: Ah * Bl
        #pragma unroll
        for (int nt = 0; nt < 4; nt++) {
            int c0 = wn + nt*8 + g;
            bt[nt][0] = BsL[buf][tig  ][c0];
            bt[nt][1] = BsL[buf][tig+4][c0];
        }
        #pragma unroll
        for (int mt = 0; mt < 4; mt++)
            #pragma unroll
            for (int nt = 0; nt < 4; nt++)
                mma16(acc[mt*4+nt], ah[mt], bt[nt]);
        // pass 3: Al * Bh
        #pragma unroll
        for (int mt = 0; mt < 4; mt++) {
            int r0 = wm + mt*16 + g;
            uint32_t al[4];
            al[0] = AsL[buf][tig  ][r0];
            al[1] = AsL[buf][tig  ][r0+8];
            al[2] = AsL[buf][tig+4][r0];
            al[3] = AsL[buf][tig+4][r0+8];
            #pragma unroll
            for (int nt = 0; nt < 4; nt++)
                mma16(acc[mt*4+nt], al, bfh[nt]);
        }

        if (more) STORE(buf ^ 1);
        __syncthreads();
        buf ^= 1;
    }

    // epilogue: c0,c1 = row g, cols 2*tig,2*tig+1; c2,c3 = row g+8
    #pragma unroll
    for (int mt = 0; mt < 4; mt++) {
        #pragma unroll
        for (int half = 0; half < 2; half++) {
            int rloc = wm + mt*16 + g + half*8;
            int rg = rowTile + rloc;
            if (rg >= Meff) continue;
            int crow = scatter ? scatter[base + rg] : (base + rg);
            size_t cb = (size_t)crow * ldc + colTile + wn + tig*2;
            #pragma unroll
            for (int nt = 0; nt < 4; nt++) {
                float x0 = acc[mt*4+nt][half*2+0];
                float x1 = acc[mt*4+nt][half*2+1];
                if (addC) {
                    const float* ap = addC + cb + nt*8;
                    x0 += ap[0]; x1 += ap[1];
                }
                *(float2*)(C + cb + nt*8) = make_float2(x0, x1);
            }
        }
    }
    #undef FETCH
    #undef STORE
}

// ---------------- attention: flash-style tiles (64 q x 32 k) ----------------
#define AQ 64
#define AK 32

__global__ void __launch_bounds__(256)
attn_kernel(const float* __restrict__ qkv, float* __restrict__ o) {
    int qt0 = blockIdx.x * AQ;
    int h   = blockIdx.y;
    int tid = threadIdx.x;
    int tx  = tid & 7;
    int ty  = tid >> 3;

    __shared__ float Qs[HD][AQ + 4];
    __shared__ float Ks[HD][AK + 4];
    __shared__ float Vs[AK][HD + 4];
    __shared__ float Ps[AK][AQ + 4];

    for (int f = tid; f < AQ * (HD/4); f += 256) {
        int r  = f >> 4;
        int dq = (f & 15) * 4;
        float4 qv = *(const float4*)(qkv + (size_t)(qt0 + r)*QKVS + h*HD + dq);
        Qs[dq+0][r] = qv.x * 0.125f;
        Qs[dq+1][r] = qv.y * 0.125f;
        Qs[dq+2][r] = qv.z * 0.125f;
        Qs[dq+3][r] = qv.w * 0.125f;
    }

    float m[2] = {-1e30f, -1e30f};
    float l[2] = {0.f, 0.f};
    float acc[2][8];
    #pragma unroll
    for (int i = 0; i < 2; i++)
        #pragma unroll
        for (int c = 0; c < 8; c++) acc[i][c] = 0.f;

    int qg0 = qt0 + ty*2;
    for (int j0 = 0; j0 <= qt0 + AQ - AK; j0 += AK) {
        __syncthreads();
        for (int f = tid; f < AK * (HD/4); f += 256) {
            int j  = f >> 4;
            int dq = (f & 15) * 4;
            float4 kv = *(const float4*)(qkv + (size_t)(j0 + j)*QKVS + DIM + h*HD + dq);
            Ks[dq+0][j] = kv.x; Ks[dq+1][j] = kv.y;
            Ks[dq+2][j] = kv.z; Ks[dq+3][j] = kv.w;
            *(float4*)&Vs[j][dq] = *(const float4*)(qkv + (size_t)(j0 + j)*QKVS + 2*DIM + h*HD + dq);
        }
        __syncthreads();

        float s[2][4];
        #pragma unroll
        for (int i = 0; i < 2; i++)
            #pragma unroll
            for (int jj = 0; jj < 4; jj++) s[i][jj] = 0.f;
        #pragma unroll 8
        for (int d = 0; d < HD; d++) {
            float a0 = Qs[d][ty*2 + 0];
            float a1 = Qs[d][ty*2 + 1];
            float4 b4 = *(const float4*)&Ks[d][tx*4];
            s[0][0] += a0*b4.x; s[0][1] += a0*b4.y; s[0][2] += a0*b4.z; s[0][3] += a0*b4.w;
            s[1][0] += a1*b4.x; s[1][1] += a1*b4.y; s[1][2] += a1*b4.z; s[1][3] += a1*b4.w;
        }
        #pragma unroll
        for (int i = 0; i < 2; i++) {
            int qg = qg0 + i;
            #pragma unroll
            for (int jj = 0; jj < 4; jj++)
                if (j0 + tx*4 + jj > qg) s[i][jj] = -1e30f;
        }
        #pragma unroll
        for (int i = 0; i < 2; i++) {
            float mx = fmaxf(fmaxf(s[i][0], s[i][1]), fmaxf(s[i][2], s[i][3]));
            mx = fmaxf(mx, __shfl_xor_sync(0xffffffff, mx, 1));
            mx = fmaxf(mx, __shfl_xor_sync(0xffffffff, mx, 2));
            mx = fmaxf(mx, __shfl_xor_sync(0xffffffff, mx, 4));
            float mn = fmaxf(m[i], mx);
            float sc = __expf(m[i] - mn);
            float p0 = __expf(s[i][0] - mn);
            float p1 = __expf(s[i][1] - mn);
            float p2 = __expf(s[i][2] - mn);
            float p3 = __expf(s[i][3] - mn);
            float rs = p0 + p1 + p2 + p3;
            rs += __shfl_xor_sync(0xffffffff, rs, 1);
            rs += __shfl_xor_sync(0xffffffff, rs, 2);
            rs += __shfl_xor_sync(0xffffffff, rs, 4);
            l[i] = l[i] * sc + rs;
            m[i] = mn;
            #pragma unroll
            for (int c = 0; c < 8; c++) acc[i][c] *= sc;
            Ps[tx*4+0][ty*2+i] = p0;
            Ps[tx*4+1][ty*2+i] = p1;
            Ps[tx*4+2][ty*2+i] = p2;
            Ps[tx*4+3][ty*2+i] = p3;
        }
        __syncthreads();

        #pragma unroll 4
        for (int j = 0; j < AK; j++) {
            float p0 = Ps[j][ty*2 + 0];
            float p1 = Ps[j][ty*2 + 1];
            float4 v0 = *(const float4*)&Vs[j][tx*4];
            float4 v1 = *(const float4*)&Vs[j][32 + tx*4];
            acc[0][0] += p0*v0.x; acc[0][1] += p0*v0.y; acc[0][2] += p0*v0.z; acc[0][3] += p0*v0.w;
            acc[0][4] += p0*v1.x; acc[0][5] += p0*v1.y; acc[0][6] += p0*v1.z; acc[0][7] += p0*v1.w;
            acc[1][0] += p1*v0.x; acc[1][1] += p1*v0.y; acc[1][2] += p1*v0.z; acc[1][3] += p1*v0.w;
            acc[1][4] += p1*v1.x; acc[1][5] += p1*v1.y; acc[1][6] += p1*v1.z; acc[1][7] += p1*v1.w;
        }
    }

    #pragma unroll
    for (int i = 0; i < 2; i++) {
        float inv = 1.f / l[i];
        float* op = o + (size_t)(qg0 + i)*DIM + h*HD;
        float4 o0 = make_float4(acc[i][0]*inv, acc[i][1]*inv, acc[i][2]*inv, acc[i][3]*inv);
        float4 o1 = make_float4(acc[i][4]*inv, acc[i][5]*inv, acc[i][6]*inv, acc[i][7]*inv);
        *(float4*)(op + tx*4)      = o0;
        *(float4*)(op + 32 + tx*4) = o1;
    }
}

// ---------------- router ----------------
__global__ void zero_cnt_kernel(int* cnt) { if (threadIdx.x < NEXP) cnt[threadIdx.x] = 0; }

__global__ void router_kernel(const float* __restrict__ x, const float* __restrict__ rw,
                              int* __restrict__ cnt, int* __restrict__ sc,
                              float* __restrict__ wt) {
    int t = blockIdx.x;
    int tid = threadIdx.x;
    int w8 = tid >> 5, lane = tid & 31;
    __shared__ float lg[NEXP];
    float s = 0.f;
    const float* xr = x + (size_t)t * DIM;
    for (int kk = lane; kk < DIM; kk += 32) s += xr[kk] * rw[kk*NEXP + w8];
    #pragma unroll
    for (int off = 16; off; off >>= 1) s += __shfl_xor_sync(0xffffffff, s, off);
    if (lane == 0) lg[w8] = s;
    __syncthreads();
    if (tid == 0) {
        float mx = lg[0];
        #pragma unroll
        for (int e = 1; e < NEXP; e++) mx = fmaxf(mx, lg[e]);
        float p[NEXP]; float se = 0.f;
        #pragma unroll
        for (int e = 0; e < NEXP; e++) { p[e] = __expf(lg[e] - mx); se += p[e]; }
        #pragma unroll
        for (int e = 0; e < NEXP; e++) p[e] /= se;
        int i0 = 0;
        #pragma unroll
        for (int e = 1; e < NEXP; e++) if (p[e] > p[i0]) i0 = e;
        int i1 = (i0 == 0) ? 1 : 0;
        #pragma unroll
        for (int e = 0; e < NEXP; e++) if (e != i0 && p[e] > p[i1]) i1 = e;
        int pos = atomicAdd(&cnt[i0], 1);
        sc[i0*SEQ + pos] = t*2 + 0; wt[i0*SEQ + pos] = p[i0];
        pos = atomicAdd(&cnt[i1], 1);
        sc[i1*SEQ + pos] = t*2 + 1; wt[i1*SEQ + pos] = p[i1];
    }
}

// prefix offsets + flatten sc/wt into compact global rows
__global__ void finalize_router(const int* __restrict__ cnt, int* __restrict__ off,
                                const int* __restrict__ sc, const float* __restrict__ wt,
                                int* __restrict__ scf, float* __restrict__ wtf) {
    __shared__ int soff[NEXP+1];
    if (threadIdx.x == 0) {
        int s = 0;
        for (int e = 0; e < NEXP; e++) { soff[e] = s; off[e] = s; s += cnt[e]; }
        soff[NEXP] = s; off[NEXP] = s;
    }
    __syncthreads();
    for (int e = 0; e < NEXP; e++) {
        int c = cnt[e], b = soff[e];
        for (int i = threadIdx.x; i < c; i += blockDim.x) {
            scf[b+i] = sc[e*SEQ+i];
            wtf[b+i] = wt[e*SEQ+i];
        }
    }
}

// ---------------- silu(g)*u*weight over flat rows ----------------
__global__ void act_kernel(float* __restrict__ g, const float* __restrict__ u,
                           const float* __restrict__ wtf) {
    int r = blockIdx.y;
    int j = blockIdx.x * 256 + threadIdx.x;
    if (j >= HID) return;
    float gv = g[(size_t)r*HID + j];
    float sv = gv / (1.f + __expf(-gv));
    g[(size_t)r*HID + j] = sv * u[(size_t)r*HID + j] * wtf[r];
}

__global__ void moe_resid_kernel(float* __restrict__ h, const float* __restrict__ y) {
    int t = blockIdx.y;
    int j = blockIdx.x * 256 + threadIdx.x;
    h[(size_t)t*DIM + j] += y[(size_t)(t*2)*DIM + j] + y[(size_t)(t*2+1)*DIM + j];
}

// ---------------- host ----------------
extern "C" void kernel_launch(void* const* d_in, const int* in_sizes, int n_in,
                              void* d_out, int out_size) {
    const int*   tokens      = (const int*)  d_in[0];
    const int*   start_pos   = (const int*)  d_in[1];
    const float* tok_emb     = (const float*)d_in[2];
    const float* wq          = (const float*)d_in[3];
    const float* wk          = (const float*)d_in[4];
    const float* wv          = (const float*)d_in[5];
    const float* wo          = (const float*)d_in[6];
    const float* attn_norm_w = (const float*)d_in[7];
    const float* ffn_norm_w  = (const float*)d_in[8];
    const float* router_w    = (const float*)d_in[9];
    const float* w1          = (const float*)d_in[10];
    const float* w2          = (const float*)d_in[11];
    const float* w3          = (const float*)d_in[12];
    const float* final_norm_w= (const float*)d_in[13];
    const float* out_w       = (const float*)d_in[14];
    float*       out         = (float*)d_out;

    float *h, *xn, *qkv, *o, *cosb, *sinb, *gb, *ub, *yb, *wt, *wtf;
    int *cnt, *offp, *sc, *scf;
    cudaGetSymbolAddress((void**)&h,    g_h);
    cudaGetSymbolAddress((void**)&xn,   g_xn);
    cudaGetSymbolAddress((void**)&qkv,  g_qkv);
    cudaGetSymbolAddress((void**)&o,    g_o);
    cudaGetSymbolAddress((void**)&cosb, g_cos);
    cudaGetSymbolAddress((void**)&sinb, g_sin);
    cudaGetSymbolAddress((void**)&gb,   g_g);
    cudaGetSymbolAddress((void**)&ub,   g_u);
    cudaGetSymbolAddress((void**)&yb,   g_y);
    cudaGetSymbolAddress((void**)&wt,   g_wt);
    cudaGetSymbolAddress((void**)&wtf,  g_wtf);
    cudaGetSymbolAddress((void**)&cnt,  g_cnt);
    cudaGetSymbolAddress((void**)&offp, g_off);
    cudaGetSymbolAddress((void**)&sc,   g_sc);
    cudaGetSymbolAddress((void**)&scf,  g_scf);

    embed_kernel<<<SEQ, 256>>>(tokens, tok_emb, h);
    rope_pre_kernel<<<SEQ, 32>>>(start_pos, cosb, sinb);

    for (int l = 0; l < NL; l++) {
        const float* wq_l = wq + (size_t)l*DIM*DIM;
        const float* wk_l = wk + (size_t)l*DIM*DIM;
        const float* wv_l = wv + (size_t)l*DIM*DIM;
        const float* wo_l = wo + (size_t)l*DIM*DIM;

        rmsnorm_kernel<<<SEQ, 256>>>(h, attn_norm_w + (size_t)l*DIM, xn);
        gemm_bf16x3<<<dim3(DIM/GBN, SEQ/GBM, 3), 256>>>(
            xn, wq_l, wk_l, wv_l, 0,
            qkv, qkv + DIM, qkv + 2*DIM, nullptr,
            SEQ, DIM, DIM, QKVS, nullptr, nullptr, nullptr, nullptr);
        rope_apply_kernel<<<SEQ, 512>>>(qkv, cosb, sinb);
        attn_kernel<<<dim3(SEQ/AQ, NH), 256>>>(qkv, o);
        gemm_bf16x3<<<dim3(DIM/GBN, SEQ/GBM, 1), 256>>>(
            o, wo_l, nullptr, nullptr, 0,
            h, nullptr, nullptr, h,
            SEQ, DIM, DIM, DIM, nullptr, nullptr, nullptr, nullptr);

        // ---- MoE ----
        rmsnorm_kernel<<<SEQ, 256>>>(h, ffn_norm_w + (size_t)l*DIM, xn);
        zero_cnt_kernel<<<1, 32>>>(cnt);
        router_kernel<<<SEQ, 256>>>(xn, router_w + (size_t)l*DIM*NEXP, cnt, sc, wt);
        finalize_router<<<1, 256>>>(cnt, offp, sc, wt, scf, wtf);

        const float* w1_l = w1 + (size_t)l*NEXP*DIM*HID;
        const float* w3_l = w3 + (size_t)l*NEXP*DIM*HID;
        const float* w2_l = w2 + (size_t)l*NEXP*HID*DIM;

        gemm_bf16x3<<<dim3(HID/GBN, SEQ/GBM, NEXP), 256>>>(
            xn, w1_l, nullptr, nullptr, (size_t)DIM*HID,
            gb, nullptr, nullptr, nullptr,
            SEQ, HID, DIM, HID, sc, nullptr, cnt, offp);
        gemm_bf16x3<<<dim3(HID/GBN, SEQ/GBM, NEXP), 256>>>(
            xn, w3_l, nullptr, nullptr, (size_t)DIM*HID,
            ub, nullptr, nullptr, nullptr,
            SEQ, HID, DIM, HID, sc, nullptr, cnt, offp);
        act_kernel<<<dim3((HID + 255)/256, 2*SEQ), 256>>>(gb, ub, wtf);
        gemm_bf16x3<<<dim3(DIM/GBN, SEQ/GBM, NEXP), 256>>>(
            gb, w2_l, nullptr, nullptr, (size_t)HID*DIM,
            yb, nullptr, nullptr, nullptr,
            SEQ, DIM, HID, DIM, nullptr, scf, cnt, offp);
        moe_resid_kernel<<<dim3(DIM/256, SEQ), 256>>>(h, yb);
    }

    rmsnorm_kernel<<<SEQ, 256>>>(h, final_norm_w, xn);
    gemm_bf16x3<<<dim3(VOCAB/GBN, SEQ/GBM, 1), 256>>>(
        xn, out_w, nullptr, nullptr, 0,
        out, nullptr, nullptr, nullptr,
        SEQ, VOCAB, DIM, VOCAB, nullptr, nullptr, nullptr, nullptr);

    (void)in_sizes; (void)n_in; (void)out_size;
}

// round 5
// speedup vs baseline: 10.2454x; 1.0881x over previous
#include <cuda_runtime.h>
#include <cuda_bf16.h>
#include <math.h>
#include <stdint.h>

#define SEQ   2048
#define DIM   1024
#define NH    16
#define HD    64
#define NEXP  8
#define HID   1408
#define VOCAB 32000
#define NL    2
#define QKVS  (3*DIM)
#define D2    (DIM/2)
#define H2    (HID/2)

// ---------------- fp32 scratch ----------------
__device__ float g_h  [SEQ*DIM];
__device__ float g_xn [SEQ*DIM];
__device__ float g_qkv[SEQ*QKVS];
__device__ float g_cos[SEQ*(HD/2)];
__device__ float g_sin[SEQ*(HD/2)];
__device__ float g_g  [2*SEQ*HID];
__device__ float g_u  [2*SEQ*HID];
__device__ float g_y  [2*SEQ*DIM];
__device__ int   g_cnt[NEXP];
__device__ int   g_off[NEXP+1];
__device__ int   g_sc [NEXP*SEQ];
__device__ float g_wt [NEXP*SEQ];
__device__ int   g_scf[2*SEQ];
__device__ float g_wtf[2*SEQ];

// ---------------- packed bf16 hi/lo scratch ----------------
__device__ uint32_t g_xnp_h[SEQ*D2],   g_xnp_l[SEQ*D2];
__device__ uint32_t g_op_h [SEQ*D2],   g_op_l [SEQ*D2];
__device__ uint32_t g_gbp_h[2*SEQ*H2], g_gbp_l[2*SEQ*H2];
__device__ uint32_t g_wqkv_h[3*D2*DIM],g_wqkv_l[3*D2*DIM];
__device__ uint32_t g_wop_h[D2*DIM],   g_wop_l[D2*DIM];
__device__ uint32_t g_w1p_h[NEXP*D2*HID], g_w1p_l[NEXP*D2*HID];
__device__ uint32_t g_w3p_h[NEXP*D2*HID], g_w3p_l[NEXP*D2*HID];
__device__ uint32_t g_w2p_h[NEXP*H2*DIM], g_w2p_l[NEXP*H2*DIM];
__device__ uint32_t g_wout_h[D2*VOCAB],   g_wout_l[D2*VOCAB];

// ---------------- helpers ----------------
__device__ __forceinline__ void split_pack(float x, float y, uint32_t& hi, uint32_t& lo) {
    __nv_bfloat16 xh = __float2bfloat16(x);
    __nv_bfloat16 yh = __float2bfloat16(y);
    __nv_bfloat16 xl = __float2bfloat16(x - __bfloat162float(xh));
    __nv_bfloat16 yl = __float2bfloat16(y - __bfloat162float(yh));
    __nv_bfloat162 h2 = __halves2bfloat162(xh, yh);
    __nv_bfloat162 l2 = __halves2bfloat162(xl, yl);
    hi = *reinterpret_cast<uint32_t*>(&h2);
    lo = *reinterpret_cast<uint32_t*>(&l2);
}

__device__ __forceinline__ void mma16(float* d, const uint32_t* a, const uint32_t* b) {
    asm volatile("mma.sync.aligned.m16n8k16.row.col.f32.bf16.bf16.f32 "
        "{%0,%1,%2,%3}, {%4,%5,%6,%7}, {%8,%9}, {%0,%1,%2,%3};\n"
        : "+f"(d[0]), "+f"(d[1]), "+f"(d[2]), "+f"(d[3])
        : "r"(a[0]), "r"(a[1]), "r"(a[2]), "r"(a[3]), "r"(b[0]), "r"(b[1]));
}

__device__ __forceinline__ void cpa16(uint32_t d, const void* s) {
    asm volatile("cp.async.cg.shared.global [%0], [%1], 16;\n" :: "r"(d), "l"(s));
}

// ---------------- embedding ----------------
__global__ void embed_kernel(const int* __restrict__ tok,
                             const float* __restrict__ emb,
                             float* __restrict__ h) {
    int t = blockIdx.x;
    int id = tok[t];
    const float* src = emb + (size_t)id * DIM;
    float* dst = h + (size_t)t * DIM;
    for (int i = threadIdx.x; i < DIM; i += blockDim.x) dst[i] = src[i];
}

// ---------------- rope ----------------
__global__ void rope_pre_kernel(const int* __restrict__ start_pos,
                                float* __restrict__ cosb, float* __restrict__ sinb) {
    int t = blockIdx.x;
    int i = threadIdx.x;
    float inv = powf(10000.0f, -(2.0f * (float)i) / (float)HD);
    float ang = (float)(*start_pos + t) * inv;
    cosb[t*32 + i] = cosf(ang);
    sinb[t*32 + i] = sinf(ang);
}

__global__ void rope_apply_kernel(float* __restrict__ qkv,
                                  const float* __restrict__ cosb,
                                  const float* __restrict__ sinb) {
    int t = blockIdx.x;
    int tid = threadIdx.x;
    int h = tid >> 5, i = tid & 31;
    float c = cosb[t*32 + i], s = sinb[t*32 + i];
    size_t base = (size_t)t*QKVS + h*HD + 2*i;
    float a = qkv[base], b = qkv[base+1];
    qkv[base]   = a*c - b*s;
    qkv[base+1] = a*s + b*c;
    a = qkv[base+DIM]; b = qkv[base+DIM+1];
    qkv[base+DIM]   = a*c - b*s;
    qkv[base+DIM+1] = a*s + b*c;
}

// ---------------- rmsnorm + pack ----------------
__global__ void rmsnorm_pack(const float* __restrict__ x, const float* __restrict__ w,
                             float* __restrict__ y,
                             uint32_t* __restrict__ ph, uint32_t* __restrict__ pl) {
    int t = blockIdx.x;
    __shared__ float red[256];
    const float* xr = x + (size_t)t * DIM;
    float s = 0.f;
    for (int i = threadIdx.x; i < DIM; i += 256) { float v = xr[i]; s += v*v; }
    red[threadIdx.x] = s; __syncthreads();
    for (int off = 128; off; off >>= 1) {
        if (threadIdx.x < off) red[threadIdx.x] += red[threadIdx.x + off];
        __syncthreads();
    }
    float r = rsqrtf(red[0] / (float)DIM + 1e-5f);
    for (int i = threadIdx.x; i < D2; i += 256) {
        float v0 = xr[2*i]   * r * w[2*i];
        float v1 = xr[2*i+1] * r * w[2*i+1];
        if (y) { y[(size_t)t*DIM + 2*i] = v0; y[(size_t)t*DIM + 2*i + 1] = v1; }
        uint32_t hh, ll; split_pack(v0, v1, hh, ll);
        ph[(size_t)t*D2 + i] = hh;
        pl[(size_t)t*D2 + i] = ll;
    }
}

// ---------------- weight pack: fp32 [K][N] -> hi/lo u32 [K/2][N] ----------------
__global__ void pack_w(const float* __restrict__ src, uint32_t* __restrict__ dh,
                       uint32_t* __restrict__ dl, int N,
                       size_t srcStride, size_t dstStride) {
    int z = blockIdx.z;
    src += (size_t)z*srcStride; dh += (size_t)z*dstStride; dl += (size_t)z*dstStride;
    int k2 = blockIdx.y;
    int n4 = blockIdx.x*blockDim.x + threadIdx.x;
    if (n4*4 >= N) return;
    const float* r0 = src + (size_t)(2*k2)*N + n4*4;
    float4 a = *(const float4*)r0;
    float4 b = *(const float4*)(r0 + N);
    uint32_t phv[4], plv[4];
    split_pack(a.x, b.x, phv[0], plv[0]);
    split_pack(a.y, b.y, phv[1], plv[1]);
    split_pack(a.z, b.z, phv[2], plv[2]);
    split_pack(a.w, b.w, phv[3], plv[3]);
    *(uint4*)(dh + (size_t)k2*N + n4*4) = *(uint4*)phv;
    *(uint4*)(dl + (size_t)k2*N + n4*4) = *(uint4*)plv;
}

// ---------------- bf16x3 GEMM, pre-packed operands, cp.async pipeline ----------------
#define BK2 16
#define PA  20
#define PB  136
#define SM_AH 0
#define SM_AL (128*2*PA)
#define SM_BH (2*SM_AL)
#define SM_BL (SM_BH + 2*BK2*PB)
#define SMEM_U32 (SM_BL + 2*BK2*PB)
#define SMEM_BYTES (SMEM_U32*4)

__global__ void __launch_bounds__(256, 2)
gemm_bf16p(const uint32_t* __restrict__ Ah, const uint32_t* __restrict__ Al,
           const uint32_t* __restrict__ Bh0, const uint32_t* __restrict__ Bl0,
           size_t strideB,
           float* __restrict__ C0, int cstep, const float* __restrict__ addC,
           int M, int N, int K2, int ldc,
           const int* __restrict__ gather, const int* __restrict__ scatter,
           const int* __restrict__ cnt, const int* __restrict__ off)
{
    extern __shared__ uint32_t sm[];
    int z = blockIdx.z;
    const uint32_t* Bh = Bh0 + (size_t)z*strideB;
    const uint32_t* Bl = Bl0 + (size_t)z*strideB;
    float* C = C0 + (size_t)z*cstep;
    int Meff = cnt ? cnt[z] : M;
    int base = off ? off[z] : 0;
    int rowTile = blockIdx.y * 128;
    if (rowTile >= Meff) return;
    int colTile = blockIdx.x * 128;

    int tid = threadIdx.x;
    int lane = tid & 31, warp = tid >> 5;
    int g = lane >> 2, tig = lane & 3;
    int wm = (warp >> 2)*64, wn = (warp & 3)*32;

    // A loader: 2 rows per thread, 16B (4 kpairs) each
    int ra  = tid >> 2;
    int ks4 = (tid & 3) * 4;
    int r0c = rowTile + ra;       if (r0c >= Meff) r0c = Meff - 1;
    int r1c = rowTile + ra + 64;  if (r1c >= Meff) r1c = Meff - 1;
    int r0m = gather ? (gather[z*SEQ + r0c] >> 1) : (base + r0c);
    int r1m = gather ? (gather[z*SEQ + r1c] >> 1) : (base + r1c);
    const uint32_t* a0h = Ah + (size_t)r0m*K2;
    const uint32_t* a1h = Ah + (size_t)r1m*K2;
    const uint32_t* a0l = Al + (size_t)r0m*K2;
    const uint32_t* a1l = Al + (size_t)r1m*K2;
    // B loader: 2 kpair-rows per thread, 16B (4 cols) each
    int kpb = tid >> 5;
    int cs4 = (tid & 31)*4;

    uint32_t sbase = (uint32_t)__cvta_generic_to_shared(sm);

    float acc[16][4];
    #pragma unroll
    for (int i = 0; i < 16; i++) { acc[i][0]=acc[i][1]=acc[i][2]=acc[i][3]=0.f; }

    auto issue = [&](int kt, int bf) {
        int kb = kt*BK2;
        cpa16(sbase + 4*(SM_AH + (bf*128 + ra)*PA + ks4),      a0h + kb + ks4);
        cpa16(sbase + 4*(SM_AH + (bf*128 + ra + 64)*PA + ks4), a1h + kb + ks4);
        cpa16(sbase + 4*(SM_AL + (bf*128 + ra)*PA + ks4),      a0l + kb + ks4);
        cpa16(sbase + 4*(SM_AL + (bf*128 + ra + 64)*PA + ks4), a1l + kb + ks4);
        cpa16(sbase + 4*(SM_BH + (bf*BK2 + kpb)*PB + cs4),     Bh + (size_t)(kb+kpb)*N + colTile + cs4);
        cpa16(sbase + 4*(SM_BH + (bf*BK2 + kpb+8)*PB + cs4),   Bh + (size_t)(kb+kpb+8)*N + colTile + cs4);
        cpa16(sbase + 4*(SM_BL + (bf*BK2 + kpb)*PB + cs4),     Bl + (size_t)(kb+kpb)*N + colTile + cs4);
        cpa16(sbase + 4*(SM_BL + (bf*BK2 + kpb+8)*PB + cs4),   Bl + (size_t)(kb+kpb+8)*N + colTile + cs4);
        asm volatile("cp.async.commit_group;\n");
    };

    int KT = K2 / BK2;
    issue(0, 0);
    int buf = 0;
    for (int kt = 0; kt < KT; kt++) {
        bool more = (kt + 1) < KT;
        if (more) {
            issue(kt+1, buf^1);
            asm volatile("cp.async.wait_group 1;\n");
        } else {
            asm volatile("cp.async.wait_group 0;\n");
        }
        __syncthreads();

        #pragma unroll
        for (int ks = 0; ks < 2; ks++) {
            int ko = ks*8;
            uint32_t ah[4][4], bh[4][2], bl[4][2];
            #pragma unroll
            for (int mt = 0; mt < 4; mt++) {
                const uint32_t* p0 = &sm[SM_AH + (buf*128 + wm + mt*16 + g)*PA + ko + tig];
                ah[mt][0] = p0[0];
                ah[mt][2] = p0[4];
                ah[mt][1] = p0[8*PA];
                ah[mt][3] = p0[8*PA + 4];
            }
            #pragma unroll
            for (int nt = 0; nt < 4; nt++) {
                int c0 = wn + nt*8 + g;
                bh[nt][0] = sm[SM_BH + (buf*BK2 + ko + tig)*PB + c0];
                bh[nt][1] = sm[SM_BH + (buf*BK2 + ko + tig + 4)*PB + c0];
                bl[nt][0] = sm[SM_BL + (buf*BK2 + ko + tig)*PB + c0];
                bl[nt][1] = sm[SM_BL + (buf*BK2 + ko + tig + 4)*PB + c0];
            }
            #pragma unroll
            for (int mt = 0; mt < 4; mt++)
                #pragma unroll
                for (int nt = 0; nt < 4; nt++)
                    mma16(acc[mt*4+nt], ah[mt], bh[nt]);
            #pragma unroll
            for (int mt = 0; mt < 4; mt++)
                #pragma unroll
                for (int nt = 0; nt < 4; nt++)
                    mma16(acc[mt*4+nt], ah[mt], bl[nt]);
            #pragma unroll
            for (int mt = 0; mt < 4; mt++) {
                const uint32_t* p0 = &sm[SM_AL + (buf*128 + wm + mt*16 + g)*PA + ko + tig];
                uint32_t al[4];
                al[0] = p0[0];
                al[2] = p0[4];
                al[1] = p0[8*PA];
                al[3] = p0[8*PA + 4];
                #pragma unroll
                for (int nt = 0; nt < 4; nt++)
                    mma16(acc[mt*4+nt], al, bh[nt]);
            }
        }
        __syncthreads();
        buf ^= 1;
    }

    #pragma unroll
    for (int mt = 0; mt < 4; mt++) {
        #pragma unroll
        for (int half = 0; half < 2; half++) {
            int rloc = wm + mt*16 + g + half*8;
            int rg = rowTile + rloc;
            if (rg >= Meff) continue;
            int crow = scatter ? scatter[base + rg] : (base + rg);
            size_t cb = (size_t)crow * ldc + colTile + wn + tig*2;
            #pragma unroll
            for (int nt = 0; nt < 4; nt++) {
                float x0 = acc[mt*4+nt][half*2+0];
                float x1 = acc[mt*4+nt][half*2+1];
                if (addC) {
                    const float* ap = addC + cb + nt*8;
                    x0 += ap[0]; x1 += ap[1];
                }
                *(float2*)(C + cb + nt*8) = make_float2(x0, x1);
            }
        }
    }
}

// ---------------- attention (flash tiles), packs O as bf16 hi/lo ----------------
#define AQ 64
#define AK 32

__global__ void __launch_bounds__(256)
attn_kernel(const float* __restrict__ qkv,
            uint32_t* __restrict__ oph, uint32_t* __restrict__ opl) {
    int qt0 = blockIdx.x * AQ;
    int h   = blockIdx.y;
    int tid = threadIdx.x;
    int tx  = tid & 7;
    int ty  = tid >> 3;

    __shared__ float Qs[HD][AQ + 4];
    __shared__ float Ks[HD][AK + 4];
    __shared__ float Vs[AK][HD + 4];
    __shared__ float Ps[AK][AQ + 4];

    for (int f = tid; f < AQ * (HD/4); f += 256) {
        int r  = f >> 4;
        int dq = (f & 15) * 4;
        float4 qv = *(const float4*)(qkv + (size_t)(qt0 + r)*QKVS + h*HD + dq);
        Qs[dq+0][r] = qv.x * 0.125f;
        Qs[dq+1][r] = qv.y * 0.125f;
        Qs[dq+2][r] = qv.z * 0.125f;
        Qs[dq+3][r] = qv.w * 0.125f;
    }

    float m[2] = {-1e30f, -1e30f};
    float l[2] = {0.f, 0.f};
    float acc[2][8];
    #pragma unroll
    for (int i = 0; i < 2; i++)
        #pragma unroll
        for (int c = 0; c < 8; c++) acc[i][c] = 0.f;

    int qg0 = qt0 + ty*2;
    for (int j0 = 0; j0 <= qt0 + AQ - AK; j0 += AK) {
        __syncthreads();
        for (int f = tid; f < AK * (HD/4); f += 256) {
            int j  = f >> 4;
            int dq = (f & 15) * 4;
            float4 kv = *(const float4*)(qkv + (size_t)(j0 + j)*QKVS + DIM + h*HD + dq);
            Ks[dq+0][j] = kv.x; Ks[dq+1][j] = kv.y;
            Ks[dq+2][j] = kv.z; Ks[dq+3][j] = kv.w;
            *(float4*)&Vs[j][dq] = *(const float4*)(qkv + (size_t)(j0 + j)*QKVS + 2*DIM + h*HD + dq);
        }
        __syncthreads();

        float s[2][4];
        #pragma unroll
        for (int i = 0; i < 2; i++)
            #pragma unroll
            for (int jj = 0; jj < 4; jj++) s[i][jj] = 0.f;
        #pragma unroll 8
        for (int d = 0; d < HD; d++) {
            float a0 = Qs[d][ty*2 + 0];
            float a1 = Qs[d][ty*2 + 1];
            float4 b4 = *(const float4*)&Ks[d][tx*4];
            s[0][0] += a0*b4.x; s[0][1] += a0*b4.y; s[0][2] += a0*b4.z; s[0][3] += a0*b4.w;
            s[1][0] += a1*b4.x; s[1][1] += a1*b4.y; s[1][2] += a1*b4.z; s[1][3] += a1*b4.w;
        }
        #pragma unroll
        for (int i = 0; i < 2; i++) {
            int qg = qg0 + i;
            #pragma unroll
            for (int jj = 0; jj < 4; jj++)
                if (j0 + tx*4 + jj > qg) s[i][jj] = -1e30f;
        }
        #pragma unroll
        for (int i = 0; i < 2; i++) {
            float mx = fmaxf(fmaxf(s[i][0], s[i][1]), fmaxf(s[i][2], s[i][3]));
            mx = fmaxf(mx, __shfl_xor_sync(0xffffffff, mx, 1));
            mx = fmaxf(mx, __shfl_xor_sync(0xffffffff, mx, 2));
            mx = fmaxf(mx, __shfl_xor_sync(0xffffffff, mx, 4));
            float mn = fmaxf(m[i], mx);
            float sc = __expf(m[i] - mn);
            float p0 = __expf(s[i][0] - mn);
            float p1 = __expf(s[i][1] - mn);
            float p2 = __expf(s[i][2] - mn);
            float p3 = __expf(s[i][3] - mn);
            float rs = p0 + p1 + p2 + p3;
            rs += __shfl_xor_sync(0xffffffff, rs, 1);
            rs += __shfl_xor_sync(0xffffffff, rs, 2);
            rs += __shfl_xor_sync(0xffffffff, rs, 4);
            l[i] = l[i] * sc + rs;
            m[i] = mn;
            #pragma unroll
            for (int c = 0; c < 8; c++) acc[i][c] *= sc;
            Ps[tx*4+0][ty*2+i] = p0;
            Ps[tx*4+1][ty*2+i] = p1;
            Ps[tx*4+2][ty*2+i] = p2;
            Ps[tx*4+3][ty*2+i] = p3;
        }
        __syncthreads();

        #pragma unroll 4
        for (int j = 0; j < AK; j++) {
            float p0 = Ps[j][ty*2 + 0];
            float p1 = Ps[j][ty*2 + 1];
            float4 v0 = *(const float4*)&Vs[j][tx*4];
            float4 v1 = *(const float4*)&Vs[j][32 + tx*4];
            acc[0][0] += p0*v0.x; acc[0][1] += p0*v0.y; acc[0][2] += p0*v0.z; acc[0][3] += p0*v0.w;
            acc[0][4] += p0*v1.x; acc[0][5] += p0*v1.y; acc[0][6] += p0*v1.z; acc[0][7] += p0*v1.w;
            acc[1][0] += p1*v0.x; acc[1][1] += p1*v0.y; acc[1][2] += p1*v0.z; acc[1][3] += p1*v0.w;
            acc[1][4] += p1*v1.x; acc[1][5] += p1*v1.y; acc[1][6] += p1*v1.z; acc[1][7] += p1*v1.w;
        }
    }

    #pragma unroll
    for (int i = 0; i < 2; i++) {
        float inv = 1.f / l[i];
        int trow = qg0 + i;
        uint32_t* oh = oph + (size_t)trow*D2 + h*(HD/2) + tx*2;
        uint32_t* ol = opl + (size_t)trow*D2 + h*(HD/2) + tx*2;
        uint32_t hh, ll;
        split_pack(acc[i][0]*inv, acc[i][1]*inv, hh, ll); oh[0]  = hh; ol[0]  = ll;
        split_pack(acc[i][2]*inv, acc[i][3]*inv, hh, ll); oh[1]  = hh; ol[1]  = ll;
        split_pack(acc[i][4]*inv, acc[i][5]*inv, hh, ll); oh[16] = hh; ol[16] = ll;
        split_pack(acc[i][6]*inv, acc[i][7]*inv, hh, ll); oh[17] = hh; ol[17] = ll;
    }
}

// ---------------- router ----------------
__global__ void zero_cnt_kernel(int* cnt) { if (threadIdx.x < NEXP) cnt[threadIdx.x] = 0; }

__global__ void router_kernel(const float* __restrict__ x, const float* __restrict__ rw,
                              int* __restrict__ cnt, int* __restrict__ sc,
                              float* __restrict__ wt) {
    int t = blockIdx.x;
    int tid = threadIdx.x;
    int w8 = tid >> 5, lane = tid & 31;
    __shared__ float lg[NEXP];
    float s = 0.f;
    const float* xr = x + (size_t)t * DIM;
    for (int kk = lane; kk < DIM; kk += 32) s += xr[kk] * rw[kk*NEXP + w8];
    #pragma unroll
    for (int off = 16; off; off >>= 1) s += __shfl_xor_sync(0xffffffff, s, off);
    if (lane == 0) lg[w8] = s;
    __syncthreads();
    if (tid == 0) {
        float mx = lg[0];
        #pragma unroll
        for (int e = 1; e < NEXP; e++) mx = fmaxf(mx, lg[e]);
        float p[NEXP]; float se = 0.f;
        #pragma unroll
        for (int e = 0; e < NEXP; e++) { p[e] = __expf(lg[e] - mx); se += p[e]; }
        #pragma unroll
        for (int e = 0; e < NEXP; e++) p[e] /= se;
        int i0 = 0;
        #pragma unroll
        for (int e = 1; e < NEXP; e++) if (p[e] > p[i0]) i0 = e;
        int i1 = (i0 == 0) ? 1 : 0;
        #pragma unroll
        for (int e = 0; e < NEXP; e++) if (e != i0 && p[e] > p[i1]) i1 = e;
        int pos = atomicAdd(&cnt[i0], 1);
        sc[i0*SEQ + pos] = t*2 + 0; wt[i0*SEQ + pos] = p[i0];
        pos = atomicAdd(&cnt[i1], 1);
        sc[i1*SEQ + pos] = t*2 + 1; wt[i1*SEQ + pos] = p[i1];
    }
}

__global__ void finalize_router(const int* __restrict__ cnt, int* __restrict__ off,
                                const int* __restrict__ sc, const float* __restrict__ wt,
                                int* __restrict__ scf, float* __restrict__ wtf) {
    __shared__ int soff[NEXP+1];
    if (threadIdx.x == 0) {
        int s = 0;
        for (int e = 0; e < NEXP; e++) { soff[e] = s; off[e] = s; s += cnt[e]; }
        soff[NEXP] = s; off[NEXP] = s;
    }
    __syncthreads();
    for (int e = 0; e < NEXP; e++) {
        int c = cnt[e], b = soff[e];
        for (int i = threadIdx.x; i < c; i += blockDim.x) {
            scf[b+i] = sc[e*SEQ+i];
            wtf[b+i] = wt[e*SEQ+i];
        }
    }
}

// ---------------- silu(g)*u*weight, packed output ----------------
__global__ void act_pack(const float* __restrict__ gbuf, const float* __restrict__ ubuf,
                         const float* __restrict__ wtf,
                         uint32_t* __restrict__ ph, uint32_t* __restrict__ pl) {
    int r  = blockIdx.y;
    int j2 = blockIdx.x*256 + threadIdx.x;
    if (j2 >= H2) return;
    float w = wtf[r];
    size_t b = (size_t)r*HID + 2*j2;
    float g0 = gbuf[b], g1 = gbuf[b+1];
    float v0 = g0 / (1.f + __expf(-g0)) * ubuf[b]   * w;
    float v1 = g1 / (1.f + __expf(-g1)) * ubuf[b+1] * w;
    uint32_t hh, ll; split_pack(v0, v1, hh, ll);
    ph[(size_t)r*H2 + j2] = hh;
    pl[(size_t)r*H2 + j2] = ll;
}

__global__ void moe_resid_kernel(float* __restrict__ h, const float* __restrict__ y) {
    int t = blockIdx.y;
    int j = blockIdx.x * 256 + threadIdx.x;
    h[(size_t)t*DIM + j] += y[(size_t)(t*2)*DIM + j] + y[(size_t)(t*2+1)*DIM + j];
}

// ---------------- host ----------------
extern "C" void kernel_launch(void* const* d_in, const int* in_sizes, int n_in,
                              void* d_out, int out_size) {
    const int*   tokens      = (const int*)  d_in[0];
    const int*   start_pos   = (const int*)  d_in[1];
    const float* tok_emb     = (const float*)d_in[2];
    const float* wq          = (const float*)d_in[3];
    const float* wk          = (const float*)d_in[4];
    const float* wv          = (const float*)d_in[5];
    const float* wo          = (const float*)d_in[6];
    const float* attn_norm_w = (const float*)d_in[7];
    const float* ffn_norm_w  = (const float*)d_in[8];
    const float* router_w    = (const float*)d_in[9];
    const float* w1          = (const float*)d_in[10];
    const float* w2          = (const float*)d_in[11];
    const float* w3          = (const float*)d_in[12];
    const float* final_norm_w= (const float*)d_in[13];
    const float* out_w       = (const float*)d_in[14];
    float*       out         = (float*)d_out;

    float *h, *xn, *qkv, *cosb, *sinb, *gb, *ub, *yb, *wt, *wtf;
    int *cnt, *offp, *sc, *scf;
    uint32_t *xnp_h, *xnp_l, *op_h, *op_l, *gbp_h, *gbp_l;
    uint32_t *wqkv_h, *wqkv_l, *wop_h, *wop_l;
    uint32_t *w1p_h, *w1p_l, *w3p_h, *w3p_l, *w2p_h, *w2p_l, *wout_h, *wout_l;

    cudaGetSymbolAddress((void**)&h,    g_h);
    cudaGetSymbolAddress((void**)&xn,   g_xn);
    cudaGetSymbolAddress((void**)&qkv,  g_qkv);
    cudaGetSymbolAddress((void**)&cosb, g_cos);
    cudaGetSymbolAddress((void**)&sinb, g_sin);
    cudaGetSymbolAddress((void**)&gb,   g_g);
    cudaGetSymbolAddress((void**)&ub,   g_u);
    cudaGetSymbolAddress((void**)&yb,   g_y);
    cudaGetSymbolAddress((void**)&wt,   g_wt);
    cudaGetSymbolAddress((void**)&wtf,  g_wtf);
    cudaGetSymbolAddress((void**)&cnt,  g_cnt);
    cudaGetSymbolAddress((void**)&offp, g_off);
    cudaGetSymbolAddress((void**)&sc,   g_sc);
    cudaGetSymbolAddress((void**)&scf,  g_scf);
    cudaGetSymbolAddress((void**)&xnp_h, g_xnp_h);  cudaGetSymbolAddress((void**)&xnp_l, g_xnp_l);
    cudaGetSymbolAddress((void**)&op_h,  g_op_h);   cudaGetSymbolAddress((void**)&op_l,  g_op_l);
    cudaGetSymbolAddress((void**)&gbp_h, g_gbp_h);  cudaGetSymbolAddress((void**)&gbp_l, g_gbp_l);
    cudaGetSymbolAddress((void**)&wqkv_h, g_wqkv_h); cudaGetSymbolAddress((void**)&wqkv_l, g_wqkv_l);
    cudaGetSymbolAddress((void**)&wop_h, g_wop_h);  cudaGetSymbolAddress((void**)&wop_l, g_wop_l);
    cudaGetSymbolAddress((void**)&w1p_h, g_w1p_h);  cudaGetSymbolAddress((void**)&w1p_l, g_w1p_l);
    cudaGetSymbolAddress((void**)&w3p_h, g_w3p_h);  cudaGetSymbolAddress((void**)&w3p_l, g_w3p_l);
    cudaGetSymbolAddress((void**)&w2p_h, g_w2p_h);  cudaGetSymbolAddress((void**)&w2p_l, g_w2p_l);
    cudaGetSymbolAddress((void**)&wout_h, g_wout_h); cudaGetSymbolAddress((void**)&wout_l, g_wout_l);

    cudaFuncSetAttribute(gemm_bf16p, cudaFuncAttributeMaxDynamicSharedMemorySize, SMEM_BYTES);

    embed_kernel<<<SEQ, 256>>>(tokens, tok_emb, h);
    rope_pre_kernel<<<SEQ, 32>>>(start_pos, cosb, sinb);
    // vocab weight pack (once)
    pack_w<<<dim3((VOCAB/4 + 255)/256, D2, 1), 256>>>(out_w, wout_h, wout_l, VOCAB, 0, 0);

    for (int l = 0; l < NL; l++) {
        // weight packs for this layer
        pack_w<<<dim3(1, D2, 1), 256>>>(wq + (size_t)l*DIM*DIM, wqkv_h,            wqkv_l,            DIM, 0, 0);
        pack_w<<<dim3(1, D2, 1), 256>>>(wk + (size_t)l*DIM*DIM, wqkv_h + D2*DIM,   wqkv_l + D2*DIM,   DIM, 0, 0);
        pack_w<<<dim3(1, D2, 1), 256>>>(wv + (size_t)l*DIM*DIM, wqkv_h + 2*D2*DIM, wqkv_l + 2*D2*DIM, DIM, 0, 0);
        pack_w<<<dim3(1, D2, 1), 256>>>(wo + (size_t)l*DIM*DIM, wop_h, wop_l, DIM, 0, 0);
        pack_w<<<dim3((HID/4 + 255)/256, D2, NEXP), 256>>>(w1 + (size_t)l*NEXP*DIM*HID, w1p_h, w1p_l, HID,
                                                           (size_t)DIM*HID, (size_t)D2*HID);
        pack_w<<<dim3((HID/4 + 255)/256, D2, NEXP), 256>>>(w3 + (size_t)l*NEXP*DIM*HID, w3p_h, w3p_l, HID,
                                                           (size_t)DIM*HID, (size_t)D2*HID);
        pack_w<<<dim3(1, H2, NEXP), 256>>>(w2 + (size_t)l*NEXP*HID*DIM, w2p_h, w2p_l, DIM,
                                           (size_t)HID*DIM, (size_t)H2*DIM);

        // ---- attention ----
        rmsnorm_pack<<<SEQ, 256>>>(h, attn_norm_w + (size_t)l*DIM, nullptr, xnp_h, xnp_l);
        gemm_bf16p<<<dim3(DIM/128, SEQ/128, 3), 256, SMEM_BYTES>>>(
            xnp_h, xnp_l, wqkv_h, wqkv_l, (size_t)D2*DIM,
            qkv, DIM, nullptr, SEQ, DIM, D2, QKVS,
            nullptr, nullptr, nullptr, nullptr);
        rope_apply_kernel<<<SEQ, 512>>>(qkv, cosb, sinb);
        attn_kernel<<<dim3(SEQ/AQ, NH), 256>>>(qkv, op_h, op_l);
        gemm_bf16p<<<dim3(DIM/128, SEQ/128, 1), 256, SMEM_BYTES>>>(
            op_h, op_l, wop_h, wop_l, 0,
            h, 0, h, SEQ, DIM, D2, DIM,
            nullptr, nullptr, nullptr, nullptr);

        // ---- MoE ----
        rmsnorm_pack<<<SEQ, 256>>>(h, ffn_norm_w + (size_t)l*DIM, xn, xnp_h, xnp_l);
        zero_cnt_kernel<<<1, 32>>>(cnt);
        router_kernel<<<SEQ, 256>>>(xn, router_w + (size_t)l*DIM*NEXP, cnt, sc, wt);
        finalize_router<<<1, 256>>>(cnt, offp, sc, wt, scf, wtf);

        gemm_bf16p<<<dim3(HID/128, SEQ/128, NEXP), 256, SMEM_BYTES>>>(
            xnp_h, xnp_l, w1p_h, w1p_l, (size_t)D2*HID,
            gb, 0, nullptr, SEQ, HID, D2, HID,
            sc, nullptr, cnt, offp);
        gemm_bf16p<<<dim3(HID/128, SEQ/128, NEXP), 256, SMEM_BYTES>>>(
            xnp_h, xnp_l, w3p_h, w3p_l, (size_t)D2*HID,
            ub, 0, nullptr, SEQ, HID, D2, HID,
            sc, nullptr, cnt, offp);
        act_pack<<<dim3((H2 + 255)/256, 2*SEQ), 256>>>(gb, ub, wtf, gbp_h, gbp_l);
        gemm_bf16p<<<dim3(DIM/128, SEQ/128, NEXP), 256, SMEM_BYTES>>>(
            gbp_h, gbp_l, w2p_h, w2p_l, (size_t)H2*DIM,
            yb, 0, nullptr, SEQ, DIM, H2, DIM,
            nullptr, scf, cnt, offp);
        moe_resid_kernel<<<dim3(DIM/256, SEQ), 256>>>(h, yb);
    }

    rmsnorm_pack<<<SEQ, 256>>>(h, final_norm_w, nullptr, xnp_h, xnp_l);
    gemm_bf16p<<<dim3(VOCAB/128, SEQ/128, 1), 256, SMEM_BYTES>>>(
        xnp_h, xnp_l, wout_h, wout_l, 0,
        out, 0, nullptr, SEQ, VOCAB, D2, VOCAB,
        nullptr, nullptr, nullptr, nullptr);

    (void)in_sizes; (void)n_in; (void)out_size;
}

// round 6
// speedup vs baseline: 11.0662x; 1.0801x over previous
#include <cuda_runtime.h>
#include <cuda_bf16.h>
#include <cuda_fp16.h>
#include <math.h>
#include <stdint.h>

#define SEQ   2048
#define DIM   1024
#define NH    16
#define HD    64
#define NEXP  8
#define HID   1408
#define VOCAB 32000
#define NL    2
#define QKVS  (3*DIM)
#define D2    (DIM/2)
#define H2    (HID/2)

// ---------------- fp32 scratch ----------------
__device__ float g_h  [SEQ*DIM];
__device__ float g_xn [SEQ*DIM];
__device__ float g_qkv[SEQ*QKVS];
__device__ float g_cos[SEQ*(HD/2)];
__device__ float g_sin[SEQ*(HD/2)];
__device__ float g_g  [2*SEQ*HID];
__device__ float g_u  [2*SEQ*HID];
__device__ float g_y  [2*SEQ*DIM];
__device__ int   g_cnt[NEXP];
__device__ int   g_off[NEXP+1];
__device__ int   g_sc [NEXP*SEQ];
__device__ float g_wt [NEXP*SEQ];
__device__ int   g_scf[2*SEQ];
__device__ float g_wtf[2*SEQ];

// ---------------- packed bf16 hi/lo scratch ----------------
__device__ uint32_t g_xnp_h[SEQ*D2],   g_xnp_l[SEQ*D2];
__device__ uint32_t g_op_h [SEQ*D2],   g_op_l [SEQ*D2];
__device__ uint32_t g_gbp_h[2*SEQ*H2], g_gbp_l[2*SEQ*H2];
__device__ uint32_t g_wqkv_h[3*D2*DIM],g_wqkv_l[3*D2*DIM];
__device__ uint32_t g_wop_h[D2*DIM],   g_wop_l[D2*DIM];
__device__ uint32_t g_w1p_h[NEXP*D2*HID], g_w1p_l[NEXP*D2*HID];
__device__ uint32_t g_w3p_h[NEXP*D2*HID], g_w3p_l[NEXP*D2*HID];
__device__ uint32_t g_w2p_h[NEXP*H2*DIM], g_w2p_l[NEXP*H2*DIM];
// fp16 single-precision vocab weights (hi only)
__device__ uint32_t g_wout16[D2*VOCAB];

// ---------------- helpers ----------------
__device__ __forceinline__ void split_pack(float x, float y, uint32_t& hi, uint32_t& lo) {
    __nv_bfloat16 xh = __float2bfloat16(x);
    __nv_bfloat16 yh = __float2bfloat16(y);
    __nv_bfloat16 xl = __float2bfloat16(x - __bfloat162float(xh));
    __nv_bfloat16 yl = __float2bfloat16(y - __bfloat162float(yh));
    __nv_bfloat162 h2 = __halves2bfloat162(xh, yh);
    __nv_bfloat162 l2 = __halves2bfloat162(xl, yl);
    hi = *reinterpret_cast<uint32_t*>(&h2);
    lo = *reinterpret_cast<uint32_t*>(&l2);
}

__device__ __forceinline__ void split_pack16(float x, float y, uint32_t& hi, uint32_t& lo) {
    __half xh = __float2half_rn(x);
    __half yh = __float2half_rn(y);
    __half xl = __float2half_rn(x - __half2float(xh));
    __half yl = __float2half_rn(y - __half2float(yh));
    __half2 h2 = __halves2half2(xh, yh);
    __half2 l2 = __halves2half2(xl, yl);
    hi = *reinterpret_cast<uint32_t*>(&h2);
    lo = *reinterpret_cast<uint32_t*>(&l2);
}

__device__ __forceinline__ uint32_t pack16(float x, float y) {
    __half2 h2 = __halves2half2(__float2half_rn(x), __float2half_rn(y));
    return *reinterpret_cast<uint32_t*>(&h2);
}

__device__ __forceinline__ void mma16(float* d, const uint32_t* a, const uint32_t* b) {
    asm volatile("mma.sync.aligned.m16n8k16.row.col.f32.bf16.bf16.f32 "
        "{%0,%1,%2,%3}, {%4,%5,%6,%7}, {%8,%9}, {%0,%1,%2,%3};\n"
        : "+f"(d[0]), "+f"(d[1]), "+f"(d[2]), "+f"(d[3])
        : "r"(a[0]), "r"(a[1]), "r"(a[2]), "r"(a[3]), "r"(b[0]), "r"(b[1]));
}

__device__ __forceinline__ void mma16h(float* d, const uint32_t* a, const uint32_t* b) {
    asm volatile("mma.sync.aligned.m16n8k16.row.col.f32.f16.f16.f32 "
        "{%0,%1,%2,%3}, {%4,%5,%6,%7}, {%8,%9}, {%0,%1,%2,%3};\n"
        : "+f"(d[0]), "+f"(d[1]), "+f"(d[2]), "+f"(d[3])
        : "r"(a[0]), "r"(a[1]), "r"(a[2]), "r"(a[3]), "r"(b[0]), "r"(b[1]));
}

__device__ __forceinline__ void cpa16(uint32_t d, const void* s) {
    asm volatile("cp.async.cg.shared.global [%0], [%1], 16;\n" :: "r"(d), "l"(s));
}

// ---------------- embedding ----------------
__global__ void embed_kernel(const int* __restrict__ tok,
                             const float* __restrict__ emb,
                             float* __restrict__ h) {
    int t = blockIdx.x;
    int id = tok[t];
    const float* src = emb + (size_t)id * DIM;
    float* dst = h + (size_t)t * DIM;
    for (int i = threadIdx.x; i < DIM; i += blockDim.x) dst[i] = src[i];
}

// ---------------- rope ----------------
__global__ void rope_pre_kernel(const int* __restrict__ start_pos,
                                float* __restrict__ cosb, float* __restrict__ sinb) {
    int t = blockIdx.x;
    int i = threadIdx.x;
    float inv = powf(10000.0f, -(2.0f * (float)i) / (float)HD);
    float ang = (float)(*start_pos + t) * inv;
    cosb[t*32 + i] = cosf(ang);
    sinb[t*32 + i] = sinf(ang);
}

__global__ void rope_apply_kernel(float* __restrict__ qkv,
                                  const float* __restrict__ cosb,
                                  const float* __restrict__ sinb) {
    int t = blockIdx.x;
    int tid = threadIdx.x;
    int h = tid >> 5, i = tid & 31;
    float c = cosb[t*32 + i], s = sinb[t*32 + i];
    size_t base = (size_t)t*QKVS + h*HD + 2*i;
    float a = qkv[base], b = qkv[base+1];
    qkv[base]   = a*c - b*s;
    qkv[base+1] = a*s + b*c;
    a = qkv[base+DIM]; b = qkv[base+DIM+1];
    qkv[base+DIM]   = a*c - b*s;
    qkv[base+DIM+1] = a*s + b*c;
}

// ---------------- rmsnorm + pack (bf16 hi/lo) ----------------
__global__ void rmsnorm_pack(const float* __restrict__ x, const float* __restrict__ w,
                             float* __restrict__ y,
                             uint32_t* __restrict__ ph, uint32_t* __restrict__ pl) {
    int t = blockIdx.x;
    __shared__ float red[256];
    const float* xr = x + (size_t)t * DIM;
    float s = 0.f;
    for (int i = threadIdx.x; i < DIM; i += 256) { float v = xr[i]; s += v*v; }
    red[threadIdx.x] = s; __syncthreads();
    for (int off = 128; off; off >>= 1) {
        if (threadIdx.x < off) red[threadIdx.x] += red[threadIdx.x + off];
        __syncthreads();
    }
    float r = rsqrtf(red[0] / (float)DIM + 1e-5f);
    for (int i = threadIdx.x; i < D2; i += 256) {
        float v0 = xr[2*i]   * r * w[2*i];
        float v1 = xr[2*i+1] * r * w[2*i+1];
        if (y) { y[(size_t)t*DIM + 2*i] = v0; y[(size_t)t*DIM + 2*i + 1] = v1; }
        uint32_t hh, ll; split_pack(v0, v1, hh, ll);
        ph[(size_t)t*D2 + i] = hh;
        pl[(size_t)t*D2 + i] = ll;
    }
}

// ---------------- rmsnorm + pack (fp16 hi/lo) for the vocab GEMM ----------------
__global__ void rmsnorm_pack_f16(const float* __restrict__ x, const float* __restrict__ w,
                                 uint32_t* __restrict__ ph, uint32_t* __restrict__ pl) {
    int t = blockIdx.x;
    __shared__ float red[256];
    const float* xr = x + (size_t)t * DIM;
    float s = 0.f;
    for (int i = threadIdx.x; i < DIM; i += 256) { float v = xr[i]; s += v*v; }
    red[threadIdx.x] = s; __syncthreads();
    for (int off = 128; off; off >>= 1) {
        if (threadIdx.x < off) red[threadIdx.x] += red[threadIdx.x + off];
        __syncthreads();
    }
    float r = rsqrtf(red[0] / (float)DIM + 1e-5f);
    for (int i = threadIdx.x; i < D2; i += 256) {
        float v0 = xr[2*i]   * r * w[2*i];
        float v1 = xr[2*i+1] * r * w[2*i+1];
        uint32_t hh, ll; split_pack16(v0, v1, hh, ll);
        ph[(size_t)t*D2 + i] = hh;
        pl[(size_t)t*D2 + i] = ll;
    }
}

// ---------------- weight pack: fp32 [K][N] -> hi/lo u32 [K/2][N] (bf16) ----------------
__global__ void pack_w(const float* __restrict__ src, uint32_t* __restrict__ dh,
                       uint32_t* __restrict__ dl, int N,
                       size_t srcStride, size_t dstStride) {
    int z = blockIdx.z;
    src += (size_t)z*srcStride; dh += (size_t)z*dstStride; dl += (size_t)z*dstStride;
    int k2 = blockIdx.y;
    int n4 = blockIdx.x*blockDim.x + threadIdx.x;
    if (n4*4 >= N) return;
    const float* r0 = src + (size_t)(2*k2)*N + n4*4;
    float4 a = *(const float4*)r0;
    float4 b = *(const float4*)(r0 + N);
    uint32_t phv[4], plv[4];
    split_pack(a.x, b.x, phv[0], plv[0]);
    split_pack(a.y, b.y, phv[1], plv[1]);
    split_pack(a.z, b.z, phv[2], plv[2]);
    split_pack(a.w, b.w, phv[3], plv[3]);
    *(uint4*)(dh + (size_t)k2*N + n4*4) = *(uint4*)phv;
    *(uint4*)(dl + (size_t)k2*N + n4*4) = *(uint4*)plv;
}

// ---------------- weight pack: fp32 [K][N] -> fp16 u32 [K/2][N] ----------------
__global__ void pack_w16(const float* __restrict__ src, uint32_t* __restrict__ dh, int N) {
    int k2 = blockIdx.y;
    int n4 = blockIdx.x*blockDim.x + threadIdx.x;
    if (n4*4 >= N) return;
    const float* r0 = src + (size_t)(2*k2)*N + n4*4;
    float4 a = *(const float4*)r0;
    float4 b = *(const float4*)(r0 + N);
    uint32_t phv[4];
    phv[0] = pack16(a.x, b.x);
    phv[1] = pack16(a.y, b.y);
    phv[2] = pack16(a.z, b.z);
    phv[3] = pack16(a.w, b.w);
    *(uint4*)(dh + (size_t)k2*N + n4*4) = *(uint4*)phv;
}

// ---------------- bf16x3 GEMM, pre-packed operands, cp.async pipeline ----------------
#define BK2 16
#define PA  20
#define PB  136
#define SM_AH 0
#define SM_AL (128*2*PA)
#define SM_BH (2*SM_AL)
#define SM_BL (SM_BH + 2*BK2*PB)
#define SMEM_U32 (SM_BL + 2*BK2*PB)
#define SMEM_BYTES (SMEM_U32*4)

__global__ void __launch_bounds__(256, 2)
gemm_bf16p(const uint32_t* __restrict__ Ah, const uint32_t* __restrict__ Al,
           const uint32_t* __restrict__ Bh0, const uint32_t* __restrict__ Bl0,
           size_t strideB,
           float* __restrict__ C0, int cstep, const float* __restrict__ addC,
           int M, int N, int K2, int ldc,
           const int* __restrict__ gather, const int* __restrict__ scatter,
           const int* __restrict__ cnt, const int* __restrict__ off)
{
    extern __shared__ uint32_t sm[];
    int z = blockIdx.z;
    const uint32_t* Bh = Bh0 + (size_t)z*strideB;
    const uint32_t* Bl = Bl0 + (size_t)z*strideB;
    float* C = C0 + (size_t)z*cstep;
    int Meff = cnt ? cnt[z] : M;
    int base = off ? off[z] : 0;
    int rowTile = blockIdx.y * 128;
    if (rowTile >= Meff) return;
    int colTile = blockIdx.x * 128;

    int tid = threadIdx.x;
    int lane = tid & 31, warp = tid >> 5;
    int g = lane >> 2, tig = lane & 3;
    int wm = (warp >> 2)*64, wn = (warp & 3)*32;

    int ra  = tid >> 2;
    int ks4 = (tid & 3) * 4;
    int r0c = rowTile + ra;       if (r0c >= Meff) r0c = Meff - 1;
    int r1c = rowTile + ra + 64;  if (r1c >= Meff) r1c = Meff - 1;
    int r0m = gather ? (gather[z*SEQ + r0c] >> 1) : (base + r0c);
    int r1m = gather ? (gather[z*SEQ + r1c] >> 1) : (base + r1c);
    const uint32_t* a0h = Ah + (size_t)r0m*K2;
    const uint32_t* a1h = Ah + (size_t)r1m*K2;
    const uint32_t* a0l = Al + (size_t)r0m*K2;
    const uint32_t* a1l = Al + (size_t)r1m*K2;
    int kpb = tid >> 5;
    int cs4 = (tid & 31)*4;

    uint32_t sbase = (uint32_t)__cvta_generic_to_shared(sm);

    float acc[16][4];
    #pragma unroll
    for (int i = 0; i < 16; i++) { acc[i][0]=acc[i][1]=acc[i][2]=acc[i][3]=0.f; }

    auto issue = [&](int kt, int bf) {
        int kb = kt*BK2;
        cpa16(sbase + 4*(SM_AH + (bf*128 + ra)*PA + ks4),      a0h + kb + ks4);
        cpa16(sbase + 4*(SM_AH + (bf*128 + ra + 64)*PA + ks4), a1h + kb + ks4);
        cpa16(sbase + 4*(SM_AL + (bf*128 + ra)*PA + ks4),      a0l + kb + ks4);
        cpa16(sbase + 4*(SM_AL + (bf*128 + ra + 64)*PA + ks4), a1l + kb + ks4);
        cpa16(sbase + 4*(SM_BH + (bf*BK2 + kpb)*PB + cs4),     Bh + (size_t)(kb+kpb)*N + colTile + cs4);
        cpa16(sbase + 4*(SM_BH + (bf*BK2 + kpb+8)*PB + cs4),   Bh + (size_t)(kb+kpb+8)*N + colTile + cs4);
        cpa16(sbase + 4*(SM_BL + (bf*BK2 + kpb)*PB + cs4),     Bl + (size_t)(kb+kpb)*N + colTile + cs4);
        cpa16(sbase + 4*(SM_BL + (bf*BK2 + kpb+8)*PB + cs4),   Bl + (size_t)(kb+kpb+8)*N + colTile + cs4);
        asm volatile("cp.async.commit_group;\n");
    };

    int KT = K2 / BK2;
    issue(0, 0);
    int buf = 0;
    for (int kt = 0; kt < KT; kt++) {
        bool more = (kt + 1) < KT;
        if (more) {
            issue(kt+1, buf^1);
            asm volatile("cp.async.wait_group 1;\n");
        } else {
            asm volatile("cp.async.wait_group 0;\n");
        }
        __syncthreads();

        #pragma unroll
        for (int ks = 0; ks < 2; ks++) {
            int ko = ks*8;
            uint32_t ah[4][4], bh[4][2], bl[4][2];
            #pragma unroll
            for (int mt = 0; mt < 4; mt++) {
                const uint32_t* p0 = &sm[SM_AH + (buf*128 + wm + mt*16 + g)*PA + ko + tig];
                ah[mt][0] = p0[0];
                ah[mt][2] = p0[4];
                ah[mt][1] = p0[8*PA];
                ah[mt][3] = p0[8*PA + 4];
            }
            #pragma unroll
            for (int nt = 0; nt < 4; nt++) {
                int c0 = wn + nt*8 + g;
                bh[nt][0] = sm[SM_BH + (buf*BK2 + ko + tig)*PB + c0];
                bh[nt][1] = sm[SM_BH + (buf*BK2 + ko + tig + 4)*PB + c0];
                bl[nt][0] = sm[SM_BL + (buf*BK2 + ko + tig)*PB + c0];
                bl[nt][1] = sm[SM_BL + (buf*BK2 + ko + tig + 4)*PB + c0];
            }
            #pragma unroll
            for (int mt = 0; mt < 4; mt++)
                #pragma unroll
                for (int nt = 0; nt < 4; nt++)
                    mma16(acc[mt*4+nt], ah[mt], bh[nt]);
            #pragma unroll
            for (int mt = 0; mt < 4; mt++)
                #pragma unroll
                for (int nt = 0; nt < 4; nt++)
                    mma16(acc[mt*4+nt], ah[mt], bl[nt]);
            #pragma unroll
            for (int mt = 0; mt < 4; mt++) {
                const uint32_t* p0 = &sm[SM_AL + (buf*128 + wm + mt*16 + g)*PA + ko + tig];
                uint32_t al[4];
                al[0] = p0[0];
                al[2] = p0[4];
                al[1] = p0[8*PA];
                al[3] = p0[8*PA + 4];
                #pragma unroll
                for (int nt = 0; nt < 4; nt++)
                    mma16(acc[mt*4+nt], al, bh[nt]);
            }
        }
        __syncthreads();
        buf ^= 1;
    }

    #pragma unroll
    for (int mt = 0; mt < 4; mt++) {
        #pragma unroll
        for (int half = 0; half < 2; half++) {
            int rloc = wm + mt*16 + g + half*8;
            int rg = rowTile + rloc;
            if (rg >= Meff) continue;
            int crow = scatter ? scatter[base + rg] : (base + rg);
            size_t cb = (size_t)crow * ldc + colTile + wn + tig*2;
            #pragma unroll
            for (int nt = 0; nt < 4; nt++) {
                float x0 = acc[mt*4+nt][half*2+0];
                float x1 = acc[mt*4+nt][half*2+1];
                if (addC) {
                    const float* ap = addC + cb + nt*8;
                    x0 += ap[0]; x1 += ap[1];
                }
                *(float2*)(C + cb + nt*8) = make_float2(x0, x1);
            }
        }
    }
}

// ---------------- fp16x2 GEMM for vocab: A hi/lo fp16, B hi fp16 only, 2 passes ----
#define V_AH 0
#define V_AL (128*2*PA)
#define V_BH (2*V_AL)
#define V_U32 (V_BH + 2*BK2*PB)
#define V_BYTES (V_U32*4)

__global__ void __launch_bounds__(256, 2)
gemm_f16v(const uint32_t* __restrict__ Ah, const uint32_t* __restrict__ Al,
          const uint32_t* __restrict__ Bh,
          float* __restrict__ C, int M, int N, int K2)
{
    extern __shared__ uint32_t sm[];
    int rowTile = blockIdx.y * 128;
    int colTile = blockIdx.x * 128;

    int tid = threadIdx.x;
    int lane = tid & 31, warp = tid >> 5;
    int g = lane >> 2, tig = lane & 3;
    int wm = (warp >> 2)*64, wn = (warp & 3)*32;

    int ra  = tid >> 2;
    int ks4 = (tid & 3) * 4;
    const uint32_t* a0h = Ah + (size_t)(rowTile + ra)*K2;
    const uint32_t* a1h = Ah + (size_t)(rowTile + ra + 64)*K2;
    const uint32_t* a0l = Al + (size_t)(rowTile + ra)*K2;
    const uint32_t* a1l = Al + (size_t)(rowTile + ra + 64)*K2;
    int kpb = tid >> 5;
    int cs4 = (tid & 31)*4;

    uint32_t sbase = (uint32_t)__cvta_generic_to_shared(sm);

    float acc[16][4];
    #pragma unroll
    for (int i = 0; i < 16; i++) { acc[i][0]=acc[i][1]=acc[i][2]=acc[i][3]=0.f; }

    auto issue = [&](int kt, int bf) {
        int kb = kt*BK2;
        cpa16(sbase + 4*(V_AH + (bf*128 + ra)*PA + ks4),      a0h + kb + ks4);
        cpa16(sbase + 4*(V_AH + (bf*128 + ra + 64)*PA + ks4), a1h + kb + ks4);
        cpa16(sbase + 4*(V_AL + (bf*128 + ra)*PA + ks4),      a0l + kb + ks4);
        cpa16(sbase + 4*(V_AL + (bf*128 + ra + 64)*PA + ks4), a1l + kb + ks4);
        cpa16(sbase + 4*(V_BH + (bf*BK2 + kpb)*PB + cs4),     Bh + (size_t)(kb+kpb)*N + colTile + cs4);
        cpa16(sbase + 4*(V_BH + (bf*BK2 + kpb+8)*PB + cs4),   Bh + (size_t)(kb+kpb+8)*N + colTile + cs4);
        asm volatile("cp.async.commit_group;\n");
    };

    int KT = K2 / BK2;
    issue(0, 0);
    int buf = 0;
    for (int kt = 0; kt < KT; kt++) {
        bool more = (kt + 1) < KT;
        if (more) {
            issue(kt+1, buf^1);
            asm volatile("cp.async.wait_group 1;\n");
        } else {
            asm volatile("cp.async.wait_group 0;\n");
        }
        __syncthreads();

        #pragma unroll
        for (int ks = 0; ks < 2; ks++) {
            int ko = ks*8;
            uint32_t ah[4][4], bh[4][2];
            #pragma unroll
            for (int mt = 0; mt < 4; mt++) {
                const uint32_t* p0 = &sm[V_AH + (buf*128 + wm + mt*16 + g)*PA + ko + tig];
                ah[mt][0] = p0[0];
                ah[mt][2] = p0[4];
                ah[mt][1] = p0[8*PA];
                ah[mt][3] = p0[8*PA + 4];
            }
            #pragma unroll
            for (int nt = 0; nt < 4; nt++) {
                int c0 = wn + nt*8 + g;
                bh[nt][0] = sm[V_BH + (buf*BK2 + ko + tig)*PB + c0];
                bh[nt][1] = sm[V_BH + (buf*BK2 + ko + tig + 4)*PB + c0];
            }
            #pragma unroll
            for (int mt = 0; mt < 4; mt++)
                #pragma unroll
                for (int nt = 0; nt < 4; nt++)
                    mma16h(acc[mt*4+nt], ah[mt], bh[nt]);
            #pragma unroll
            for (int mt = 0; mt < 4; mt++) {
                const uint32_t* p0 = &sm[V_AL + (buf*128 + wm + mt*16 + g)*PA + ko + tig];
                uint32_t al[4];
                al[0] = p0[0];
                al[2] = p0[4];
                al[1] = p0[8*PA];
                al[3] = p0[8*PA + 4];
                #pragma unroll
                for (int nt = 0; nt < 4; nt++)
                    mma16h(acc[mt*4+nt], al, bh[nt]);
            }
        }
        __syncthreads();
        buf ^= 1;
    }

    #pragma unroll
    for (int mt = 0; mt < 4; mt++) {
        #pragma unroll
        for (int half = 0; half < 2; half++) {
            int rg = rowTile + wm + mt*16 + g + half*8;
            size_t cb = (size_t)rg * N + colTile + wn + tig*2;
            #pragma unroll
            for (int nt = 0; nt < 4; nt++) {
                *(float2*)(C + cb + nt*8) =
                    make_float2(acc[mt*4+nt][half*2+0], acc[mt*4+nt][half*2+1]);
            }
        }
    }
}

// ---------------- attention (flash tiles), packs O as bf16 hi/lo ----------------
#define AQ 64
#define AK 32

__global__ void __launch_bounds__(256)
attn_kernel(const float* __restrict__ qkv,
            uint32_t* __restrict__ oph, uint32_t* __restrict__ opl) {
    int qt0 = blockIdx.x * AQ;
    int h   = blockIdx.y;
    int tid = threadIdx.x;
    int tx  = tid & 7;
    int ty  = tid >> 3;

    __shared__ float Qs[HD][AQ + 4];
    __shared__ float Ks[HD][AK + 4];
    __shared__ float Vs[AK][HD + 4];
    __shared__ float Ps[AK][AQ + 4];

    for (int f = tid; f < AQ * (HD/4); f += 256) {
        int r  = f >> 4;
        int dq = (f & 15) * 4;
        float4 qv = *(const float4*)(qkv + (size_t)(qt0 + r)*QKVS + h*HD + dq);
        Qs[dq+0][r] = qv.x * 0.125f;
        Qs[dq+1][r] = qv.y * 0.125f;
        Qs[dq+2][r] = qv.z * 0.125f;
        Qs[dq+3][r] = qv.w * 0.125f;
    }

    float m[2] = {-1e30f, -1e30f};
    float l[2] = {0.f, 0.f};
    float acc[2][8];
    #pragma unroll
    for (int i = 0; i < 2; i++)
        #pragma unroll
        for (int c = 0; c < 8; c++) acc[i][c] = 0.f;

    int qg0 = qt0 + ty*2;
    for (int j0 = 0; j0 <= qt0 + AQ - AK; j0 += AK) {
        __syncthreads();
        for (int f = tid; f < AK * (HD/4); f += 256) {
            int j  = f >> 4;
            int dq = (f & 15) * 4;
            float4 kv = *(const float4*)(qkv + (size_t)(j0 + j)*QKVS + DIM + h*HD + dq);
            Ks[dq+0][j] = kv.x; Ks[dq+1][j] = kv.y;
            Ks[dq+2][j] = kv.z; Ks[dq+3][j] = kv.w;
            *(float4*)&Vs[j][dq] = *(const float4*)(qkv + (size_t)(j0 + j)*QKVS + 2*DIM + h*HD + dq);
        }
        __syncthreads();

        float s[2][4];
        #pragma unroll
        for (int i = 0; i < 2; i++)
            #pragma unroll
            for (int jj = 0; jj < 4; jj++) s[i][jj] = 0.f;
        #pragma unroll 8
        for (int d = 0; d < HD; d++) {
            float a0 = Qs[d][ty*2 + 0];
            float a1 = Qs[d][ty*2 + 1];
            float4 b4 = *(const float4*)&Ks[d][tx*4];
            s[0][0] += a0*b4.x; s[0][1] += a0*b4.y; s[0][2] += a0*b4.z; s[0][3] += a0*b4.w;
            s[1][0] += a1*b4.x; s[1][1] += a1*b4.y; s[1][2] += a1*b4.z; s[1][3] += a1*b4.w;
        }
        #pragma unroll
        for (int i = 0; i < 2; i++) {
            int qg = qg0 + i;
            #pragma unroll
            for (int jj = 0; jj < 4; jj++)
                if (j0 + tx*4 + jj > qg) s[i][jj] = -1e30f;
        }
        #pragma unroll
        for (int i = 0; i < 2; i++) {
            float mx = fmaxf(fmaxf(s[i][0], s[i][1]), fmaxf(s[i][2], s[i][3]));
            mx = fmaxf(mx, __shfl_xor_sync(0xffffffff, mx, 1));
            mx = fmaxf(mx, __shfl_xor_sync(0xffffffff, mx, 2));
            mx = fmaxf(mx, __shfl_xor_sync(0xffffffff, mx, 4));
            float mn = fmaxf(m[i], mx);
            float sc = __expf(m[i] - mn);
            float p0 = __expf(s[i][0] - mn);
            float p1 = __expf(s[i][1] - mn);
            float p2 = __expf(s[i][2] - mn);
            float p3 = __expf(s[i][3] - mn);
            float rs = p0 + p1 + p2 + p3;
            rs += __shfl_xor_sync(0xffffffff, rs, 1);
            rs += __shfl_xor_sync(0xffffffff, rs, 2);
            rs += __shfl_xor_sync(0xffffffff, rs, 4);
            l[i] = l[i] * sc + rs;
            m[i] = mn;
            #pragma unroll
            for (int c = 0; c < 8; c++) acc[i][c] *= sc;
            Ps[tx*4+0][ty*2+i] = p0;
            Ps[tx*4+1][ty*2+i] = p1;
            Ps[tx*4+2][ty*2+i] = p2;
            Ps[tx*4+3][ty*2+i] = p3;
        }
        __syncthreads();

        #pragma unroll 4
        for (int j = 0; j < AK; j++) {
            float p0 = Ps[j][ty*2 + 0];
            float p1 = Ps[j][ty*2 + 1];
            float4 v0 = *(const float4*)&Vs[j][tx*4];
            float4 v1 = *(const float4*)&Vs[j][32 + tx*4];
            acc[0][0] += p0*v0.x; acc[0][1] += p0*v0.y; acc[0][2] += p0*v0.z; acc[0][3] += p0*v0.w;
            acc[0][4] += p0*v1.x; acc[0][5] += p0*v1.y; acc[0][6] += p0*v1.z; acc[0][7] += p0*v1.w;
            acc[1][0] += p1*v0.x; acc[1][1] += p1*v0.y; acc[1][2] += p1*v0.z; acc[1][3] += p1*v0.w;
            acc[1][4] += p1*v1.x; acc[1][5] += p1*v1.y; acc[1][6] += p1*v1.z; acc[1][7] += p1*v1.w;
        }
    }

    #pragma unroll
    for (int i = 0; i < 2; i++) {
        float inv = 1.f / l[i];
        int trow = qg0 + i;
        uint32_t* oh = oph + (size_t)trow*D2 + h*(HD/2) + tx*2;
        uint32_t* ol = opl + (size_t)trow*D2 + h*(HD/2) + tx*2;
        uint32_t hh, ll;
        split_pack(acc[i][0]*inv, acc[i][1]*inv, hh, ll); oh[0]  = hh; ol[0]  = ll;
        split_pack(acc[i][2]*inv, acc[i][3]*inv, hh, ll); oh[1]  = hh; ol[1]  = ll;
        split_pack(acc[i][4]*inv, acc[i][5]*inv, hh, ll); oh[16] = hh; ol[16] = ll;
        split_pack(acc[i][6]*inv, acc[i][7]*inv, hh, ll); oh[17] = hh; ol[17] = ll;
    }
}

// ---------------- router ----------------
__global__ void zero_cnt_kernel(int* cnt) { if (threadIdx.x < NEXP) cnt[threadIdx.x] = 0; }

__global__ void router_kernel(const float* __restrict__ x, const float* __restrict__ rw,
                              int* __restrict__ cnt, int* __restrict__ sc,
                              float* __restrict__ wt) {
    int t = blockIdx.x;
    int tid = threadIdx.x;
    int w8 = tid >> 5, lane = tid & 31;
    __shared__ float lg[NEXP];
    float s = 0.f;
    const float* xr = x + (size_t)t * DIM;
    for (int kk = lane; kk < DIM; kk += 32) s += xr[kk] * rw[kk*NEXP + w8];
    #pragma unroll
    for (int off = 16; off; off >>= 1) s += __shfl_xor_sync(0xffffffff, s, off);
    if (lane == 0) lg[w8] = s;
    __syncthreads();
    if (tid == 0) {
        float mx = lg[0];
        #pragma unroll
        for (int e = 1; e < NEXP; e++) mx = fmaxf(mx, lg[e]);
        float p[NEXP]; float se = 0.f;
        #pragma unroll
        for (int e = 0; e < NEXP; e++) { p[e] = __expf(lg[e] - mx); se += p[e]; }
        #pragma unroll
        for (int e = 0; e < NEXP; e++) p[e] /= se;
        int i0 = 0;
        #pragma unroll
        for (int e = 1; e < NEXP; e++) if (p[e] > p[i0]) i0 = e;
        int i1 = (i0 == 0) ? 1 : 0;
        #pragma unroll
        for (int e = 0; e < NEXP; e++) if (e != i0 && p[e] > p[i1]) i1 = e;
        int pos = atomicAdd(&cnt[i0], 1);
        sc[i0*SEQ + pos] = t*2 + 0; wt[i0*SEQ + pos] = p[i0];
        pos = atomicAdd(&cnt[i1], 1);
        sc[i1*SEQ + pos] = t*2 + 1; wt[i1*SEQ + pos] = p[i1];
    }
}

__global__ void finalize_router(const int* __restrict__ cnt, int* __restrict__ off,
                                const int* __restrict__ sc, const float* __restrict__ wt,
                                int* __restrict__ scf, float* __restrict__ wtf) {
    __shared__ int soff[NEXP+1];
    if (threadIdx.x == 0) {
        int s = 0;
        for (int e = 0; e < NEXP; e++) { soff[e] = s; off[e] = s; s += cnt[e]; }
        soff[NEXP] = s; off[NEXP] = s;
    }
    __syncthreads();
    for (int e = 0; e < NEXP; e++) {
        int c = cnt[e], b = soff[e];
        for (int i = threadIdx.x; i < c; i += blockDim.x) {
            scf[b+i] = sc[e*SEQ+i];
            wtf[b+i] = wt[e*SEQ+i];
        }
    }
}

// ---------------- silu(g)*u*weight, packed output ----------------
__global__ void act_pack(const float* __restrict__ gbuf, const float* __restrict__ ubuf,
                         const float* __restrict__ wtf,
                         uint32_t* __restrict__ ph, uint32_t* __restrict__ pl) {
    int r  = blockIdx.y;
    int j2 = blockIdx.x*256 + threadIdx.x;
    if (j2 >= H2) return;
    float w = wtf[r];
    size_t b = (size_t)r*HID + 2*j2;
    float g0 = gbuf[b], g1 = gbuf[b+1];
    float v0 = g0 / (1.f + __expf(-g0)) * ubuf[b]   * w;
    float v1 = g1 / (1.f + __expf(-g1)) * ubuf[b+1] * w;
    uint32_t hh, ll; split_pack(v0, v1, hh, ll);
    ph[(size_t)r*H2 + j2] = hh;
    pl[(size_t)r*H2 + j2] = ll;
}

__global__ void moe_resid_kernel(float* __restrict__ h, const float* __restrict__ y) {
    int t = blockIdx.y;
    int j = blockIdx.x * 256 + threadIdx.x;
    h[(size_t)t*DIM + j] += y[(size_t)(t*2)*DIM + j] + y[(size_t)(t*2+1)*DIM + j];
}

// ---------------- host ----------------
extern "C" void kernel_launch(void* const* d_in, const int* in_sizes, int n_in,
                              void* d_out, int out_size) {
    const int*   tokens      = (const int*)  d_in[0];
    const int*   start_pos   = (const int*)  d_in[1];
    const float* tok_emb     = (const float*)d_in[2];
    const float* wq          = (const float*)d_in[3];
    const float* wk          = (const float*)d_in[4];
    const float* wv          = (const float*)d_in[5];
    const float* wo          = (const float*)d_in[6];
    const float* attn_norm_w = (const float*)d_in[7];
    const float* ffn_norm_w  = (const float*)d_in[8];
    const float* router_w    = (const float*)d_in[9];
    const float* w1          = (const float*)d_in[10];
    const float* w2          = (const float*)d_in[11];
    const float* w3          = (const float*)d_in[12];
    const float* final_norm_w= (const float*)d_in[13];
    const float* out_w       = (const float*)d_in[14];
    float*       out         = (float*)d_out;

    float *h, *xn, *qkv, *cosb, *sinb, *gb, *ub, *yb, *wt, *wtf;
    int *cnt, *offp, *sc, *scf;
    uint32_t *xnp_h, *xnp_l, *op_h, *op_l, *gbp_h, *gbp_l;
    uint32_t *wqkv_h, *wqkv_l, *wop_h, *wop_l;
    uint32_t *w1p_h, *w1p_l, *w3p_h, *w3p_l, *w2p_h, *w2p_l, *wout16;

    cudaGetSymbolAddress((void**)&h,    g_h);
    cudaGetSymbolAddress((void**)&xn,   g_xn);
    cudaGetSymbolAddress((void**)&qkv,  g_qkv);
    cudaGetSymbolAddress((void**)&cosb, g_cos);
    cudaGetSymbolAddress((void**)&sinb, g_sin);
    cudaGetSymbolAddress((void**)&gb,   g_g);
    cudaGetSymbolAddress((void**)&ub,   g_u);
    cudaGetSymbolAddress((void**)&yb,   g_y);
    cudaGetSymbolAddress((void**)&wt,   g_wt);
    cudaGetSymbolAddress((void**)&wtf,  g_wtf);
    cudaGetSymbolAddress((void**)&cnt,  g_cnt);
    cudaGetSymbolAddress((void**)&offp, g_off);
    cudaGetSymbolAddress((void**)&sc,   g_sc);
    cudaGetSymbolAddress((void**)&scf,  g_scf);
    cudaGetSymbolAddress((void**)&xnp_h, g_xnp_h);  cudaGetSymbolAddress((void**)&xnp_l, g_xnp_l);
    cudaGetSymbolAddress((void**)&op_h,  g_op_h);   cudaGetSymbolAddress((void**)&op_l,  g_op_l);
    cudaGetSymbolAddress((void**)&gbp_h, g_gbp_h);  cudaGetSymbolAddress((void**)&gbp_l, g_gbp_l);
    cudaGetSymbolAddress((void**)&wqkv_h, g_wqkv_h); cudaGetSymbolAddress((void**)&wqkv_l, g_wqkv_l);
    cudaGetSymbolAddress((void**)&wop_h, g_wop_h);  cudaGetSymbolAddress((void**)&wop_l, g_wop_l);
    cudaGetSymbolAddress((void**)&w1p_h, g_w1p_h);  cudaGetSymbolAddress((void**)&w1p_l, g_w1p_l);
    cudaGetSymbolAddress((void**)&w3p_h, g_w3p_h);  cudaGetSymbolAddress((void**)&w3p_l, g_w3p_l);
    cudaGetSymbolAddress((void**)&w2p_h, g_w2p_h);  cudaGetSymbolAddress((void**)&w2p_l, g_w2p_l);
    cudaGetSymbolAddress((void**)&wout16, g_wout16);

    cudaFuncSetAttribute(gemm_bf16p, cudaFuncAttributeMaxDynamicSharedMemorySize, SMEM_BYTES);
    cudaFuncSetAttribute(gemm_f16v,  cudaFuncAttributeMaxDynamicSharedMemorySize, V_BYTES);

    embed_kernel<<<SEQ, 256>>>(tokens, tok_emb, h);
    rope_pre_kernel<<<SEQ, 32>>>(start_pos, cosb, sinb);
    // vocab weight pack: fp16 hi only
    pack_w16<<<dim3((VOCAB/4 + 255)/256, D2, 1), 256>>>(out_w, wout16, VOCAB);

    for (int l = 0; l < NL; l++) {
        pack_w<<<dim3(1, D2, 1), 256>>>(wq + (size_t)l*DIM*DIM, wqkv_h,            wqkv_l,            DIM, 0, 0);
        pack_w<<<dim3(1, D2, 1), 256>>>(wk + (size_t)l*DIM*DIM, wqkv_h + D2*DIM,   wqkv_l + D2*DIM,   DIM, 0, 0);
        pack_w<<<dim3(1, D2, 1), 256>>>(wv + (size_t)l*DIM*DIM, wqkv_h + 2*D2*DIM, wqkv_l + 2*D2*DIM, DIM, 0, 0);
        pack_w<<<dim3(1, D2, 1), 256>>>(wo + (size_t)l*DIM*DIM, wop_h, wop_l, DIM, 0, 0);
        pack_w<<<dim3((HID/4 + 255)/256, D2, NEXP), 256>>>(w1 + (size_t)l*NEXP*DIM*HID, w1p_h, w1p_l, HID,
                                                           (size_t)DIM*HID, (size_t)D2*HID);
        pack_w<<<dim3((HID/4 + 255)/256, D2, NEXP), 256>>>(w3 + (size_t)l*NEXP*DIM*HID, w3p_h, w3p_l, HID,
                                                           (size_t)DIM*HID, (size_t)D2*HID);
        pack_w<<<dim3(1, H2, NEXP), 256>>>(w2 + (size_t)l*NEXP*HID*DIM, w2p_h, w2p_l, DIM,
                                           (size_t)HID*DIM, (size_t)H2*DIM);

        // ---- attention ----
        rmsnorm_pack<<<SEQ, 256>>>(h, attn_norm_w + (size_t)l*DIM, nullptr, xnp_h, xnp_l);
        gemm_bf16p<<<dim3(DIM/128, SEQ/128, 3), 256, SMEM_BYTES>>>(
            xnp_h, xnp_l, wqkv_h, wqkv_l, (size_t)D2*DIM,
            qkv, DIM, nullptr, SEQ, DIM, D2, QKVS,
            nullptr, nullptr, nullptr, nullptr);
        rope_apply_kernel<<<SEQ, 512>>>(qkv, cosb, sinb);
        attn_kernel<<<dim3(SEQ/AQ, NH), 256>>>(qkv, op_h, op_l);
        gemm_bf16p<<<dim3(DIM/128, SEQ/128, 1), 256, SMEM_BYTES>>>(
            op_h, op_l, wop_h, wop_l, 0,
            h, 0, h, SEQ, DIM, D2, DIM,
            nullptr, nullptr, nullptr, nullptr);

        // ---- MoE ----
        rmsnorm_pack<<<SEQ, 256>>>(h, ffn_norm_w + (size_t)l*DIM, xn, xnp_h, xnp_l);
        zero_cnt_kernel<<<1, 32>>>(cnt);
        router_kernel<<<SEQ, 256>>>(xn, router_w + (size_t)l*DIM*NEXP, cnt, sc, wt);
        finalize_router<<<1, 256>>>(cnt, offp, sc, wt, scf, wtf);

        gemm_bf16p<<<dim3(HID/128, SEQ/128, NEXP), 256, SMEM_BYTES>>>(
            xnp_h, xnp_l, w1p_h, w1p_l, (size_t)D2*HID,
            gb, 0, nullptr, SEQ, HID, D2, HID,
            sc, nullptr, cnt, offp);
        gemm_bf16p<<<dim3(HID/128, SEQ/128, NEXP), 256, SMEM_BYTES>>>(
            xnp_h, xnp_l, w3p_h, w3p_l, (size_t)D2*HID,
            ub, 0, nullptr, SEQ, HID, D2, HID,
            sc, nullptr, cnt, offp);
        act_pack<<<dim3((H2 + 255)/256, 2*SEQ), 256>>>(gb, ub, wtf, gbp_h, gbp_l);
        gemm_bf16p<<<dim3(DIM/128, SEQ/128, NEXP), 256, SMEM_BYTES>>>(
            gbp_h, gbp_l, w2p_h, w2p_l, (size_t)H2*DIM,
            yb, 0, nullptr, SEQ, DIM, H2, DIM,
            nullptr, scf, cnt, offp);
        moe_resid_kernel<<<dim3(DIM/256, SEQ), 256>>>(h, yb);
    }

    rmsnorm_pack_f16<<<SEQ, 256>>>(h, final_norm_w, xnp_h, xnp_l);
    gemm_f16v<<<dim3(VOCAB/128, SEQ/128, 1), 256, V_BYTES>>>(
        xnp_h, xnp_l, wout16, out, SEQ, VOCAB, D2);

    (void)in_sizes; (void)n_in; (void)out_size;
}

// round 7
// speedup vs baseline: 12.3989x; 1.1204x over previous
#include <cuda_runtime.h>
#include <cuda_bf16.h>
#include <cuda_fp16.h>
#include <math.h>
#include <stdint.h>

#define SEQ   2048
#define DIM   1024
#define NH    16
#define HD    64
#define NEXP  8
#define HID   1408
#define VOCAB 32000
#define NL    2
#define QKVS  (3*DIM)
#define D2    (DIM/2)
#define H2    (HID/2)
#define HID2  (2*HID)

// ---------------- fp32 scratch ----------------
__device__ float g_h  [SEQ*DIM];
__device__ float g_xn [SEQ*DIM];
__device__ float g_qkv[SEQ*QKVS];
__device__ float g_cos[SEQ*(HD/2)];
__device__ float g_sin[SEQ*(HD/2)];
__device__ float g_gu [2*SEQ*HID2];          // fused w1|w3 output [4096][2816]
__device__ float g_y  [2*SEQ*DIM];
__device__ int   g_cnt[NEXP];
__device__ int   g_off[NEXP+1];
__device__ int   g_sc [NEXP*SEQ];
__device__ float g_wt [NEXP*SEQ];
__device__ int   g_scf[2*SEQ];
__device__ float g_wtf[2*SEQ];

// ---------------- packed bf16 hi/lo scratch ----------------
__device__ uint32_t g_xnp_h[SEQ*D2],   g_xnp_l[SEQ*D2];
__device__ uint32_t g_op_h [SEQ*D2],   g_op_l [SEQ*D2];
__device__ uint32_t g_gbp_h[2*SEQ*H2], g_gbp_l[2*SEQ*H2];
__device__ uint32_t g_wqkv_h[3*D2*DIM],g_wqkv_l[3*D2*DIM];
__device__ uint32_t g_wop_h[D2*DIM],   g_wop_l[D2*DIM];
__device__ uint32_t g_w13_h[NEXP*D2*HID2], g_w13_l[NEXP*D2*HID2];   // w1 cols [0,1408), w3 cols [1408,2816)
__device__ uint32_t g_w2p_h[NEXP*H2*DIM], g_w2p_l[NEXP*H2*DIM];
__device__ uint32_t g_wout16[D2*VOCAB];   // fp16 hi only

// ---------------- helpers ----------------
__device__ __forceinline__ void split_pack(float x, float y, uint32_t& hi, uint32_t& lo) {
    __nv_bfloat16 xh = __float2bfloat16(x);
    __nv_bfloat16 yh = __float2bfloat16(y);
    __nv_bfloat16 xl = __float2bfloat16(x - __bfloat162float(xh));
    __nv_bfloat16 yl = __float2bfloat16(y - __bfloat162float(yh));
    __nv_bfloat162 h2 = __halves2bfloat162(xh, yh);
    __nv_bfloat162 l2 = __halves2bfloat162(xl, yl);
    hi = *reinterpret_cast<uint32_t*>(&h2);
    lo = *reinterpret_cast<uint32_t*>(&l2);
}

__device__ __forceinline__ uint32_t pack16(float x, float y) {
    __half2 h2 = __halves2half2(__float2half_rn(x), __float2half_rn(y));
    return *reinterpret_cast<uint32_t*>(&h2);
}

__device__ __forceinline__ void mma16(float* d, const uint32_t* a, const uint32_t* b) {
    asm volatile("mma.sync.aligned.m16n8k16.row.col.f32.bf16.bf16.f32 "
        "{%0,%1,%2,%3}, {%4,%5,%6,%7}, {%8,%9}, {%0,%1,%2,%3};\n"
        : "+f"(d[0]), "+f"(d[1]), "+f"(d[2]), "+f"(d[3])
        : "r"(a[0]), "r"(a[1]), "r"(a[2]), "r"(a[3]), "r"(b[0]), "r"(b[1]));
}

__device__ __forceinline__ void mma16h(float* d, const uint32_t* a, const uint32_t* b) {
    asm volatile("mma.sync.aligned.m16n8k16.row.col.f32.f16.f16.f32 "
        "{%0,%1,%2,%3}, {%4,%5,%6,%7}, {%8,%9}, {%0,%1,%2,%3};\n"
        : "+f"(d[0]), "+f"(d[1]), "+f"(d[2]), "+f"(d[3])
        : "r"(a[0]), "r"(a[1]), "r"(a[2]), "r"(a[3]), "r"(b[0]), "r"(b[1]));
}

__device__ __forceinline__ void cpa16(uint32_t d, const void* s) {
    asm volatile("cp.async.cg.shared.global [%0], [%1], 16;\n" :: "r"(d), "l"(s));
}

// ---------------- embedding ----------------
__global__ void embed_kernel(const int* __restrict__ tok,
                             const float* __restrict__ emb,
                             float* __restrict__ h) {
    int t = blockIdx.x;
    int id = tok[t];
    const float* src = emb + (size_t)id * DIM;
    float* dst = h + (size_t)t * DIM;
    for (int i = threadIdx.x; i < DIM; i += blockDim.x) dst[i] = src[i];
}

// ---------------- rope ----------------
__global__ void rope_pre_kernel(const int* __restrict__ start_pos,
                                float* __restrict__ cosb, float* __restrict__ sinb) {
    int t = blockIdx.x;
    int i = threadIdx.x;
    float inv = powf(10000.0f, -(2.0f * (float)i) / (float)HD);
    float ang = (float)(*start_pos + t) * inv;
    cosb[t*32 + i] = cosf(ang);
    sinb[t*32 + i] = sinf(ang);
}

__global__ void rope_apply_kernel(float* __restrict__ qkv,
                                  const float* __restrict__ cosb,
                                  const float* __restrict__ sinb) {
    int t = blockIdx.x;
    int tid = threadIdx.x;
    int h = tid >> 5, i = tid & 31;
    float c = cosb[t*32 + i], s = sinb[t*32 + i];
    size_t base = (size_t)t*QKVS + h*HD + 2*i;
    float a = qkv[base], b = qkv[base+1];
    qkv[base]   = a*c - b*s;
    qkv[base+1] = a*s + b*c;
    a = qkv[base+DIM]; b = qkv[base+DIM+1];
    qkv[base+DIM]   = a*c - b*s;
    qkv[base+DIM+1] = a*s + b*c;
}

// ------ rmsnorm (+optional MoE residual fuse) + bf16 hi/lo pack ------
__global__ void rmsnorm_pack(float* __restrict__ x, const float* __restrict__ yres,
                             const float* __restrict__ w,
                             float* __restrict__ xnout,
                             uint32_t* __restrict__ ph, uint32_t* __restrict__ pl) {
    int t = blockIdx.x;
    __shared__ float xb[DIM];
    __shared__ float red[256];
    float* xr = x + (size_t)t * DIM;
    float s = 0.f;
    for (int i = threadIdx.x; i < DIM; i += 256) {
        float v = xr[i];
        if (yres) {
            v += yres[(size_t)(2*t)*DIM + i] + yres[(size_t)(2*t+1)*DIM + i];
            xr[i] = v;
        }
        xb[i] = v;
        s += v*v;
    }
    red[threadIdx.x] = s; __syncthreads();
    for (int off = 128; off; off >>= 1) {
        if (threadIdx.x < off) red[threadIdx.x] += red[threadIdx.x + off];
        __syncthreads();
    }
    float r = rsqrtf(red[0] / (float)DIM + 1e-5f);
    for (int i = threadIdx.x; i < D2; i += 256) {
        float v0 = xb[2*i]   * r * w[2*i];
        float v1 = xb[2*i+1] * r * w[2*i+1];
        if (xnout) { xnout[(size_t)t*DIM + 2*i] = v0; xnout[(size_t)t*DIM + 2*i + 1] = v1; }
        uint32_t hh, ll; split_pack(v0, v1, hh, ll);
        ph[(size_t)t*D2 + i] = hh;
        pl[(size_t)t*D2 + i] = ll;
    }
}

// ------ rmsnorm (+residual) + fp16 hi pack (vocab path) ------
__global__ void rmsnorm_pack_f16(float* __restrict__ x, const float* __restrict__ yres,
                                 const float* __restrict__ w,
                                 uint32_t* __restrict__ ph) {
    int t = blockIdx.x;
    __shared__ float xb[DIM];
    __shared__ float red[256];
    float* xr = x + (size_t)t * DIM;
    float s = 0.f;
    for (int i = threadIdx.x; i < DIM; i += 256) {
        float v = xr[i];
        if (yres) v += yres[(size_t)(2*t)*DIM + i] + yres[(size_t)(2*t+1)*DIM + i];
        xb[i] = v;
        s += v*v;
    }
    red[threadIdx.x] = s; __syncthreads();
    for (int off = 128; off; off >>= 1) {
        if (threadIdx.x < off) red[threadIdx.x] += red[threadIdx.x + off];
        __syncthreads();
    }
    float r = rsqrtf(red[0] / (float)DIM + 1e-5f);
    for (int i = threadIdx.x; i < D2; i += 256) {
        float v0 = xb[2*i]   * r * w[2*i];
        float v1 = xb[2*i+1] * r * w[2*i+1];
        ph[(size_t)t*D2 + i] = pack16(v0, v1);
    }
}

// ---- weight pack: fp32 [K][N] -> hi/lo u32 [K/2][ldd] at colOff, 8 cols/thread ----
__global__ void pack_w8(const float* __restrict__ src, uint32_t* __restrict__ dh,
                        uint32_t* __restrict__ dl, int N, int ldd, int colOff,
                        size_t srcStride, size_t dstStride) {
    int z = blockIdx.z;
    src += (size_t)z*srcStride; dh += (size_t)z*dstStride; dl += (size_t)z*dstStride;
    int k2 = blockIdx.y;
    int n8 = (blockIdx.x*blockDim.x + threadIdx.x)*8;
    if (n8 >= N) return;
    const float* r0 = src + (size_t)(2*k2)*N + n8;
    float4 a0 = *(const float4*)r0;
    float4 a1 = *(const float4*)(r0 + 4);
    float4 b0 = *(const float4*)(r0 + N);
    float4 b1 = *(const float4*)(r0 + N + 4);
    uint32_t ph[8], pl[8];
    split_pack(a0.x, b0.x, ph[0], pl[0]);
    split_pack(a0.y, b0.y, ph[1], pl[1]);
    split_pack(a0.z, b0.z, ph[2], pl[2]);
    split_pack(a0.w, b0.w, ph[3], pl[3]);
    split_pack(a1.x, b1.x, ph[4], pl[4]);
    split_pack(a1.y, b1.y, ph[5], pl[5]);
    split_pack(a1.z, b1.z, ph[6], pl[6]);
    split_pack(a1.w, b1.w, ph[7], pl[7]);
    uint32_t* oh = dh + (size_t)k2*ldd + colOff + n8;
    uint32_t* ol = dl + (size_t)k2*ldd + colOff + n8;
    *(uint4*)oh     = *(uint4*)&ph[0];
    *(uint4*)(oh+4) = *(uint4*)&ph[4];
    *(uint4*)ol     = *(uint4*)&pl[0];
    *(uint4*)(ol+4) = *(uint4*)&pl[4];
}

// ---- vocab weight pack: fp32 [K][N] -> fp16 u32 [K/2][N], 8 cols/thread ----
__global__ void pack_w16(const float* __restrict__ src, uint32_t* __restrict__ dh, int N) {
    int k2 = blockIdx.y;
    int n8 = (blockIdx.x*blockDim.x + threadIdx.x)*8;
    if (n8 >= N) return;
    const float* r0 = src + (size_t)(2*k2)*N + n8;
    float4 a0 = *(const float4*)r0;
    float4 a1 = *(const float4*)(r0 + 4);
    float4 b0 = *(const float4*)(r0 + N);
    float4 b1 = *(const float4*)(r0 + N + 4);
    uint32_t ph[8];
    ph[0] = pack16(a0.x, b0.x); ph[1] = pack16(a0.y, b0.y);
    ph[2] = pack16(a0.z, b0.z); ph[3] = pack16(a0.w, b0.w);
    ph[4] = pack16(a1.x, b1.x); ph[5] = pack16(a1.y, b1.y);
    ph[6] = pack16(a1.z, b1.z); ph[7] = pack16(a1.w, b1.w);
    uint32_t* oh = dh + (size_t)k2*N + n8;
    *(uint4*)oh     = *(uint4*)&ph[0];
    *(uint4*)(oh+4) = *(uint4*)&ph[4];
}

// ---------------- bf16x3 GEMM, pre-packed operands, cp.async pipeline ----------------
#define BK2 16
#define PA  20
#define PB  136
#define SM_AH 0
#define SM_AL (128*2*PA)
#define SM_BH (2*SM_AL)
#define SM_BL (SM_BH + 2*BK2*PB)
#define SMEM_U32 (SM_BL + 2*BK2*PB)
#define SMEM_BYTES (SMEM_U32*4)

__global__ void __launch_bounds__(256, 2)
gemm_bf16p(const uint32_t* __restrict__ Ah, const uint32_t* __restrict__ Al,
           const uint32_t* __restrict__ Bh0, const uint32_t* __restrict__ Bl0,
           size_t strideB,
           float* __restrict__ C0, int cstep, const float* __restrict__ addC,
           int M, int N, int K2, int ldc,
           const int* __restrict__ gather, const int* __restrict__ scatter,
           const int* __restrict__ cnt, const int* __restrict__ off)
{
    extern __shared__ uint32_t sm[];
    int z = blockIdx.z;
    const uint32_t* Bh = Bh0 + (size_t)z*strideB;
    const uint32_t* Bl = Bl0 + (size_t)z*strideB;
    float* C = C0 + (size_t)z*cstep;
    int Meff = cnt ? cnt[z] : M;
    int base = off ? off[z] : 0;
    int rowTile = blockIdx.y * 128;
    if (rowTile >= Meff) return;
    int colTile = blockIdx.x * 128;

    int tid = threadIdx.x;
    int lane = tid & 31, warp = tid >> 5;
    int g = lane >> 2, tig = lane & 3;
    int wm = (warp >> 2)*64, wn = (warp & 3)*32;

    int ra  = tid >> 2;
    int ks4 = (tid & 3) * 4;
    int r0c = rowTile + ra;       if (r0c >= Meff) r0c = Meff - 1;
    int r1c = rowTile + ra + 64;  if (r1c >= Meff) r1c = Meff - 1;
    int r0m = gather ? (gather[z*SEQ + r0c] >> 1) : (base + r0c);
    int r1m = gather ? (gather[z*SEQ + r1c] >> 1) : (base + r1c);
    const uint32_t* a0h = Ah + (size_t)r0m*K2;
    const uint32_t* a1h = Ah + (size_t)r1m*K2;
    const uint32_t* a0l = Al + (size_t)r0m*K2;
    const uint32_t* a1l = Al + (size_t)r1m*K2;
    int kpb = tid >> 5;
    int cs4 = (tid & 31)*4;

    uint32_t sbase = (uint32_t)__cvta_generic_to_shared(sm);

    float acc[16][4];
    #pragma unroll
    for (int i = 0; i < 16; i++) { acc[i][0]=acc[i][1]=acc[i][2]=acc[i][3]=0.f; }

    auto issue = [&](int kt, int bf) {
        int kb = kt*BK2;
        cpa16(sbase + 4*(SM_AH + (bf*128 + ra)*PA + ks4),      a0h + kb + ks4);
        cpa16(sbase + 4*(SM_AH + (bf*128 + ra + 64)*PA + ks4), a1h + kb + ks4);
        cpa16(sbase + 4*(SM_AL + (bf*128 + ra)*PA + ks4),      a0l + kb + ks4);
        cpa16(sbase + 4*(SM_AL + (bf*128 + ra + 64)*PA + ks4), a1l + kb + ks4);
        cpa16(sbase + 4*(SM_BH + (bf*BK2 + kpb)*PB + cs4),     Bh + (size_t)(kb+kpb)*N + colTile + cs4);
        cpa16(sbase + 4*(SM_BH + (bf*BK2 + kpb+8)*PB + cs4),   Bh + (size_t)(kb+kpb+8)*N + colTile + cs4);
        cpa16(sbase + 4*(SM_BL + (bf*BK2 + kpb)*PB + cs4),     Bl + (size_t)(kb+kpb)*N + colTile + cs4);
        cpa16(sbase + 4*(SM_BL + (bf*BK2 + kpb+8)*PB + cs4),   Bl + (size_t)(kb+kpb+8)*N + colTile + cs4);
        asm volatile("cp.async.commit_group;\n");
    };

    int KT = K2 / BK2;
    issue(0, 0);
    int buf = 0;
    for (int kt = 0; kt < KT; kt++) {
        bool more = (kt + 1) < KT;
        if (more) {
            issue(kt+1, buf^1);
            asm volatile("cp.async.wait_group 1;\n");
        } else {
            asm volatile("cp.async.wait_group 0;\n");
        }
        __syncthreads();

        #pragma unroll
        for (int ks = 0; ks < 2; ks++) {
            int ko = ks*8;
            uint32_t ah[4][4], bh[4][2], bl[4][2];
            #pragma unroll
            for (int mt = 0; mt < 4; mt++) {
                const uint32_t* p0 = &sm[SM_AH + (buf*128 + wm + mt*16 + g)*PA + ko + tig];
                ah[mt][0] = p0[0];
                ah[mt][2] = p0[4];
                ah[mt][1] = p0[8*PA];
                ah[mt][3] = p0[8*PA + 4];
            }
            #pragma unroll
            for (int nt = 0; nt < 4; nt++) {
                int c0 = wn + nt*8 + g;
                bh[nt][0] = sm[SM_BH + (buf*BK2 + ko + tig)*PB + c0];
                bh[nt][1] = sm[SM_BH + (buf*BK2 + ko + tig + 4)*PB + c0];
                bl[nt][0] = sm[SM_BL + (buf*BK2 + ko + tig)*PB + c0];
                bl[nt][1] = sm[SM_BL + (buf*BK2 + ko + tig + 4)*PB + c0];
            }
            #pragma unroll
            for (int mt = 0; mt < 4; mt++)
                #pragma unroll
                for (int nt = 0; nt < 4; nt++)
                    mma16(acc[mt*4+nt], ah[mt], bh[nt]);
            #pragma unroll
            for (int mt = 0; mt < 4; mt++)
                #pragma unroll
                for (int nt = 0; nt < 4; nt++)
                    mma16(acc[mt*4+nt], ah[mt], bl[nt]);
            #pragma unroll
            for (int mt = 0; mt < 4; mt++) {
                const uint32_t* p0 = &sm[SM_AL + (buf*128 + wm + mt*16 + g)*PA + ko + tig];
                uint32_t al[4];
                al[0] = p0[0];
                al[2] = p0[4];
                al[1] = p0[8*PA];
                al[3] = p0[8*PA + 4];
                #pragma unroll
                for (int nt = 0; nt < 4; nt++)
                    mma16(acc[mt*4+nt], al, bh[nt]);
            }
        }
        __syncthreads();
        buf ^= 1;
    }

    #pragma unroll
    for (int mt = 0; mt < 4; mt++) {
        #pragma unroll
        for (int half = 0; half < 2; half++) {
            int rloc = wm + mt*16 + g + half*8;
            int rg = rowTile + rloc;
            if (rg >= Meff) continue;
            int crow = scatter ? scatter[base + rg] : (base + rg);
            size_t cb = (size_t)crow * ldc + colTile + wn + tig*2;
            #pragma unroll
            for (int nt = 0; nt < 4; nt++) {
                float x0 = acc[mt*4+nt][half*2+0];
                float x1 = acc[mt*4+nt][half*2+1];
                if (addC) {
                    const float* ap = addC + cb + nt*8;
                    x0 += ap[0]; x1 += ap[1];
                }
                *(float2*)(C + cb + nt*8) = make_float2(x0, x1);
            }
        }
    }
}

// ---------------- fp16 single-pass GEMM for vocab ----------------
#define V_AH 0
#define V_BH (128*2*PA)
#define V_U32 (V_BH + 2*BK2*PB)
#define V_BYTES (V_U32*4)

__global__ void __launch_bounds__(256, 2)
gemm_f16v(const uint32_t* __restrict__ Ah, const uint32_t* __restrict__ Bh,
          float* __restrict__ C, int M, int N, int K2)
{
    extern __shared__ uint32_t sm[];
    int rowTile = blockIdx.y * 128;
    int colTile = blockIdx.x * 128;

    int tid = threadIdx.x;
    int lane = tid & 31, warp = tid >> 5;
    int g = lane >> 2, tig = lane & 3;
    int wm = (warp >> 2)*64, wn = (warp & 3)*32;

    int ra  = tid >> 2;
    int ks4 = (tid & 3) * 4;
    const uint32_t* a0h = Ah + (size_t)(rowTile + ra)*K2;
    const uint32_t* a1h = Ah + (size_t)(rowTile + ra + 64)*K2;
    int kpb = tid >> 5;
    int cs4 = (tid & 31)*4;

    uint32_t sbase = (uint32_t)__cvta_generic_to_shared(sm);

    float acc[16][4];
    #pragma unroll
    for (int i = 0; i < 16; i++) { acc[i][0]=acc[i][1]=acc[i][2]=acc[i][3]=0.f; }

    auto issue = [&](int kt, int bf) {
        int kb = kt*BK2;
        cpa16(sbase + 4*(V_AH + (bf*128 + ra)*PA + ks4),      a0h + kb + ks4);
        cpa16(sbase + 4*(V_AH + (bf*128 + ra + 64)*PA + ks4), a1h + kb + ks4);
        cpa16(sbase + 4*(V_BH + (bf*BK2 + kpb)*PB + cs4),     Bh + (size_t)(kb+kpb)*N + colTile + cs4);
        cpa16(sbase + 4*(V_BH + (bf*BK2 + kpb+8)*PB + cs4),   Bh + (size_t)(kb+kpb+8)*N + colTile + cs4);
        asm volatile("cp.async.commit_group;\n");
    };

    int KT = K2 / BK2;
    issue(0, 0);
    int buf = 0;
    for (int kt = 0; kt < KT; kt++) {
        bool more = (kt + 1) < KT;
        if (more) {
            issue(kt+1, buf^1);
            asm volatile("cp.async.wait_group 1;\n");
        } else {
            asm volatile("cp.async.wait_group 0;\n");
        }
        __syncthreads();

        #pragma unroll
        for (int ks = 0; ks < 2; ks++) {
            int ko = ks*8;
            uint32_t ah[4][4], bh[4][2];
            #pragma unroll
            for (int mt = 0; mt < 4; mt++) {
                const uint32_t* p0 = &sm[V_AH + (buf*128 + wm + mt*16 + g)*PA + ko + tig];
                ah[mt][0] = p0[0];
                ah[mt][2] = p0[4];
                ah[mt][1] = p0[8*PA];
                ah[mt][3] = p0[8*PA + 4];
            }
            #pragma unroll
            for (int nt = 0; nt < 4; nt++) {
                int c0 = wn + nt*8 + g;
                bh[nt][0] = sm[V_BH + (buf*BK2 + ko + tig)*PB + c0];
                bh[nt][1] = sm[V_BH + (buf*BK2 + ko + tig + 4)*PB + c0];
            }
            #pragma unroll
            for (int mt = 0; mt < 4; mt++)
                #pragma unroll
                for (int nt = 0; nt < 4; nt++)
                    mma16h(acc[mt*4+nt], ah[mt], bh[nt]);
        }
        __syncthreads();
        buf ^= 1;
    }

    #pragma unroll
    for (int mt = 0; mt < 4; mt++) {
        #pragma unroll
        for (int half = 0; half < 2; half++) {
            int rg = rowTile + wm + mt*16 + g + half*8;
            size_t cb = (size_t)rg * N + colTile + wn + tig*2;
            #pragma unroll
            for (int nt = 0; nt < 4; nt++) {
                *(float2*)(C + cb + nt*8) =
                    make_float2(acc[mt*4+nt][half*2+0], acc[mt*4+nt][half*2+1]);
            }
        }
    }
}

// ---------------- attention (flash tiles), packs O as bf16 hi/lo ----------------
#define AQ 64
#define AK 32

__global__ void __launch_bounds__(256)
attn_kernel(const float* __restrict__ qkv,
            uint32_t* __restrict__ oph, uint32_t* __restrict__ opl) {
    int qt0 = blockIdx.x * AQ;
    int h   = blockIdx.y;
    int tid = threadIdx.x;
    int tx  = tid & 7;
    int ty  = tid >> 3;

    __shared__ float Qs[HD][AQ + 4];
    __shared__ float Ks[HD][AK + 4];
    __shared__ float Vs[AK][HD + 4];
    __shared__ float Ps[AK][AQ + 4];

    for (int f = tid; f < AQ * (HD/4); f += 256) {
        int r  = f >> 4;
        int dq = (f & 15) * 4;
        float4 qv = *(const float4*)(qkv + (size_t)(qt0 + r)*QKVS + h*HD + dq);
        Qs[dq+0][r] = qv.x * 0.125f;
        Qs[dq+1][r] = qv.y * 0.125f;
        Qs[dq+2][r] = qv.z * 0.125f;
        Qs[dq+3][r] = qv.w * 0.125f;
    }

    float m[2] = {-1e30f, -1e30f};
    float l[2] = {0.f, 0.f};
    float acc[2][8];
    #pragma unroll
    for (int i = 0; i < 2; i++)
        #pragma unroll
        for (int c = 0; c < 8; c++) acc[i][c] = 0.f;

    int qg0 = qt0 + ty*2;
    for (int j0 = 0; j0 <= qt0 + AQ - AK; j0 += AK) {
        __syncthreads();
        for (int f = tid; f < AK * (HD/4); f += 256) {
            int j  = f >> 4;
            int dq = (f & 15) * 4;
            float4 kv = *(const float4*)(qkv + (size_t)(j0 + j)*QKVS + DIM + h*HD + dq);
            Ks[dq+0][j] = kv.x; Ks[dq+1][j] = kv.y;
            Ks[dq+2][j] = kv.z; Ks[dq+3][j] = kv.w;
            *(float4*)&Vs[j][dq] = *(const float4*)(qkv + (size_t)(j0 + j)*QKVS + 2*DIM + h*HD + dq);
        }
        __syncthreads();

        float s[2][4];
        #pragma unroll
        for (int i = 0; i < 2; i++)
            #pragma unroll
            for (int jj = 0; jj < 4; jj++) s[i][jj] = 0.f;
        #pragma unroll 8
        for (int d = 0; d < HD; d++) {
            float a0 = Qs[d][ty*2 + 0];
            float a1 = Qs[d][ty*2 + 1];
            float4 b4 = *(const float4*)&Ks[d][tx*4];
            s[0][0] += a0*b4.x; s[0][1] += a0*b4.y; s[0][2] += a0*b4.z; s[0][3] += a0*b4.w;
            s[1][0] += a1*b4.x; s[1][1] += a1*b4.y; s[1][2] += a1*b4.z; s[1][3] += a1*b4.w;
        }
        #pragma unroll
        for (int i = 0; i < 2; i++) {
            int qg = qg0 + i;
            #pragma unroll
            for (int jj = 0; jj < 4; jj++)
                if (j0 + tx*4 + jj > qg) s[i][jj] = -1e30f;
        }
        #pragma unroll
        for (int i = 0; i < 2; i++) {
            float mx = fmaxf(fmaxf(s[i][0], s[i][1]), fmaxf(s[i][2], s[i][3]));
            mx = fmaxf(mx, __shfl_xor_sync(0xffffffff, mx, 1));
            mx = fmaxf(mx, __shfl_xor_sync(0xffffffff, mx, 2));
            mx = fmaxf(mx, __shfl_xor_sync(0xffffffff, mx, 4));
            float mn = fmaxf(m[i], mx);
            float sc = __expf(m[i] - mn);
            float p0 = __expf(s[i][0] - mn);
            float p1 = __expf(s[i][1] - mn);
            float p2 = __expf(s[i][2] - mn);
            float p3 = __expf(s[i][3] - mn);
            float rs = p0 + p1 + p2 + p3;
            rs += __shfl_xor_sync(0xffffffff, rs, 1);
            rs += __shfl_xor_sync(0xffffffff, rs, 2);
            rs += __shfl_xor_sync(0xffffffff, rs, 4);
            l[i] = l[i] * sc + rs;
            m[i] = mn;
            #pragma unroll
            for (int c = 0; c < 8; c++) acc[i][c] *= sc;
            Ps[tx*4+0][ty*2+i] = p0;
            Ps[tx*4+1][ty*2+i] = p1;
            Ps[tx*4+2][ty*2+i] = p2;
            Ps[tx*4+3][ty*2+i] = p3;
        }
        __syncthreads();

        #pragma unroll 4
        for (int j = 0; j < AK; j++) {
            float p0 = Ps[j][ty*2 + 0];
            float p1 = Ps[j][ty*2 + 1];
            float4 v0 = *(const float4*)&Vs[j][tx*4];
            float4 v1 = *(const float4*)&Vs[j][32 + tx*4];
            acc[0][0] += p0*v0.x; acc[0][1] += p0*v0.y; acc[0][2] += p0*v0.z; acc[0][3] += p0*v0.w;
            acc[0][4] += p0*v1.x; acc[0][5] += p0*v1.y; acc[0][6] += p0*v1.z; acc[0][7] += p0*v1.w;
            acc[1][0] += p1*v0.x; acc[1][1] += p1*v0.y; acc[1][2] += p1*v0.z; acc[1][3] += p1*v0.w;
            acc[1][4] += p1*v1.x; acc[1][5] += p1*v1.y; acc[1][6] += p1*v1.z; acc[1][7] += p1*v1.w;
        }
    }

    #pragma unroll
    for (int i = 0; i < 2; i++) {
        float inv = 1.f / l[i];
        int trow = qg0 + i;
        uint32_t* oh = oph + (size_t)trow*D2 + h*(HD/2) + tx*2;
        uint32_t* ol = opl + (size_t)trow*D2 + h*(HD/2) + tx*2;
        uint32_t hh, ll;
        split_pack(acc[i][0]*inv, acc[i][1]*inv, hh, ll); oh[0]  = hh; ol[0]  = ll;
        split_pack(acc[i][2]*inv, acc[i][3]*inv, hh, ll); oh[1]  = hh; ol[1]  = ll;
        split_pack(acc[i][4]*inv, acc[i][5]*inv, hh, ll); oh[16] = hh; ol[16] = ll;
        split_pack(acc[i][6]*inv, acc[i][7]*inv, hh, ll); oh[17] = hh; ol[17] = ll;
    }
}

// ---------------- router ----------------
__global__ void zero_cnt_kernel(int* cnt) { if (threadIdx.x < NEXP) cnt[threadIdx.x] = 0; }

__global__ void router_kernel(const float* __restrict__ x, const float* __restrict__ rw,
                              int* __restrict__ cnt, int* __restrict__ sc,
                              float* __restrict__ wt) {
    int t = blockIdx.x;
    int tid = threadIdx.x;
    int w8 = tid >> 5, lane = tid & 31;
    __shared__ float lg[NEXP];
    float s = 0.f;
    const float* xr = x + (size_t)t * DIM;
    for (int kk = lane; kk < DIM; kk += 32) s += xr[kk] * rw[kk*NEXP + w8];
    #pragma unroll
    for (int off = 16; off; off >>= 1) s += __shfl_xor_sync(0xffffffff, s, off);
    if (lane == 0) lg[w8] = s;
    __syncthreads();
    if (tid == 0) {
        float mx = lg[0];
        #pragma unroll
        for (int e = 1; e < NEXP; e++) mx = fmaxf(mx, lg[e]);
        float p[NEXP]; float se = 0.f;
        #pragma unroll
        for (int e = 0; e < NEXP; e++) { p[e] = __expf(lg[e] - mx); se += p[e]; }
        #pragma unroll
        for (int e = 0; e < NEXP; e++) p[e] /= se;
        int i0 = 0;
        #pragma unroll
        for (int e = 1; e < NEXP; e++) if (p[e] > p[i0]) i0 = e;
        int i1 = (i0 == 0) ? 1 : 0;
        #pragma unroll
        for (int e = 0; e < NEXP; e++) if (e != i0 && p[e] > p[i1]) i1 = e;
        int pos = atomicAdd(&cnt[i0], 1);
        sc[i0*SEQ + pos] = t*2 + 0; wt[i0*SEQ + pos] = p[i0];
        pos = atomicAdd(&cnt[i1], 1);
        sc[i1*SEQ + pos] = t*2 + 1; wt[i1*SEQ + pos] = p[i1];
    }
}

__global__ void finalize_router(const int* __restrict__ cnt, int* __restrict__ off,
                                const int* __restrict__ sc, const float* __restrict__ wt,
                                int* __restrict__ scf, float* __restrict__ wtf) {
    __shared__ int soff[NEXP+1];
    if (threadIdx.x == 0) {
        int s = 0;
        for (int e = 0; e < NEXP; e++) { soff[e] = s; off[e] = s; s += cnt[e]; }
        soff[NEXP] = s; off[NEXP] = s;
    }
    __syncthreads();
    for (int e = 0; e < NEXP; e++) {
        int c = cnt[e], b = soff[e];
        for (int i = threadIdx.x; i < c; i += blockDim.x) {
            scf[b+i] = sc[e*SEQ+i];
            wtf[b+i] = wt[e*SEQ+i];
        }
    }
}

// ------- silu(g)*u*weight from fused [r][2816] buffer, packed output -------
__global__ void act_pack(const float* __restrict__ gu, const float* __restrict__ wtf,
                         uint32_t* __restrict__ ph, uint32_t* __restrict__ pl) {
    int r  = blockIdx.y;
    int j2 = blockIdx.x*256 + threadIdx.x;
    if (j2 >= H2) return;
    float w = wtf[r];
    size_t b = (size_t)r*HID2 + 2*j2;
    float g0 = gu[b],       g1 = gu[b+1];
    float u0 = gu[b+HID],   u1 = gu[b+HID+1];
    float v0 = g0 / (1.f + __expf(-g0)) * u0 * w;
    float v1 = g1 / (1.f + __expf(-g1)) * u1 * w;
    uint32_t hh, ll; split_pack(v0, v1, hh, ll);
    ph[(size_t)r*H2 + j2] = hh;
    pl[(size_t)r*H2 + j2] = ll;
}

// ---------------- host ----------------
extern "C" void kernel_launch(void* const* d_in, const int* in_sizes, int n_in,
                              void* d_out, int out_size) {
    const int*   tokens      = (const int*)  d_in[0];
    const int*   start_pos   = (const int*)  d_in[1];
    const float* tok_emb     = (const float*)d_in[2];
    const float* wq          = (const float*)d_in[3];
    const float* wk          = (const float*)d_in[4];
    const float* wv          = (const float*)d_in[5];
    const float* wo          = (const float*)d_in[6];
    const float* attn_norm_w = (const float*)d_in[7];
    const float* ffn_norm_w  = (const float*)d_in[8];
    const float* router_w    = (const float*)d_in[9];
    const float* w1          = (const float*)d_in[10];
    const float* w2          = (const float*)d_in[11];
    const float* w3          = (const float*)d_in[12];
    const float* final_norm_w= (const float*)d_in[13];
    const float* out_w       = (const float*)d_in[14];
    float*       out         = (float*)d_out;

    float *h, *xn, *qkv, *cosb, *sinb, *gu, *yb, *wt, *wtf;
    int *cnt, *offp, *sc, *scf;
    uint32_t *xnp_h, *xnp_l, *op_h, *op_l, *gbp_h, *gbp_l;
    uint32_t *wqkv_h, *wqkv_l, *wop_h, *wop_l;
    uint32_t *w13_h, *w13_l, *w2p_h, *w2p_l, *wout16;

    cudaGetSymbolAddress((void**)&h,    g_h);
    cudaGetSymbolAddress((void**)&xn,   g_xn);
    cudaGetSymbolAddress((void**)&qkv,  g_qkv);
    cudaGetSymbolAddress((void**)&cosb, g_cos);
    cudaGetSymbolAddress((void**)&sinb, g_sin);
    cudaGetSymbolAddress((void**)&gu,   g_gu);
    cudaGetSymbolAddress((void**)&yb,   g_y);
    cudaGetSymbolAddress((void**)&wt,   g_wt);
    cudaGetSymbolAddress((void**)&wtf,  g_wtf);
    cudaGetSymbolAddress((void**)&cnt,  g_cnt);
    cudaGetSymbolAddress((void**)&offp, g_off);
    cudaGetSymbolAddress((void**)&sc,   g_sc);
    cudaGetSymbolAddress((void**)&scf,  g_scf);
    cudaGetSymbolAddress((void**)&xnp_h, g_xnp_h);  cudaGetSymbolAddress((void**)&xnp_l, g_xnp_l);
    cudaGetSymbolAddress((void**)&op_h,  g_op_h);   cudaGetSymbolAddress((void**)&op_l,  g_op_l);
    cudaGetSymbolAddress((void**)&gbp_h, g_gbp_h);  cudaGetSymbolAddress((void**)&gbp_l, g_gbp_l);
    cudaGetSymbolAddress((void**)&wqkv_h, g_wqkv_h); cudaGetSymbolAddress((void**)&wqkv_l, g_wqkv_l);
    cudaGetSymbolAddress((void**)&wop_h, g_wop_h);  cudaGetSymbolAddress((void**)&wop_l, g_wop_l);
    cudaGetSymbolAddress((void**)&w13_h, g_w13_h);  cudaGetSymbolAddress((void**)&w13_l, g_w13_l);
    cudaGetSymbolAddress((void**)&w2p_h, g_w2p_h);  cudaGetSymbolAddress((void**)&w2p_l, g_w2p_l);
    cudaGetSymbolAddress((void**)&wout16, g_wout16);

    cudaFuncSetAttribute(gemm_bf16p, cudaFuncAttributeMaxDynamicSharedMemorySize, SMEM_BYTES);
    cudaFuncSetAttribute(gemm_f16v,  cudaFuncAttributeMaxDynamicSharedMemorySize, V_BYTES);

    embed_kernel<<<SEQ, 256>>>(tokens, tok_emb, h);
    rope_pre_kernel<<<SEQ, 32>>>(start_pos, cosb, sinb);
    pack_w16<<<dim3((VOCAB/8 + 127)/128, D2), 128>>>(out_w, wout16, VOCAB);

    for (int l = 0; l < NL; l++) {
        // weight packs for this layer
        pack_w8<<<dim3(1, D2, 1), 128>>>(wq + (size_t)l*DIM*DIM, wqkv_h,            wqkv_l,            DIM, DIM, 0, 0, 0);
        pack_w8<<<dim3(1, D2, 1), 128>>>(wk + (size_t)l*DIM*DIM, wqkv_h + D2*DIM,   wqkv_l + D2*DIM,   DIM, DIM, 0, 0, 0);
        pack_w8<<<dim3(1, D2, 1), 128>>>(wv + (size_t)l*DIM*DIM, wqkv_h + 2*D2*DIM, wqkv_l + 2*D2*DIM, DIM, DIM, 0, 0, 0);
        pack_w8<<<dim3(1, D2, 1), 128>>>(wo + (size_t)l*DIM*DIM, wop_h, wop_l, DIM, DIM, 0, 0, 0);
        pack_w8<<<dim3(2, D2, NEXP), 128>>>(w1 + (size_t)l*NEXP*DIM*HID, w13_h, w13_l, HID, HID2, 0,
                                            (size_t)DIM*HID, (size_t)D2*HID2);
        pack_w8<<<dim3(2, D2, NEXP), 128>>>(w3 + (size_t)l*NEXP*DIM*HID, w13_h, w13_l, HID, HID2, HID,
                                            (size_t)DIM*HID, (size_t)D2*HID2);
        pack_w8<<<dim3(1, H2, NEXP), 128>>>(w2 + (size_t)l*NEXP*HID*DIM, w2p_h, w2p_l, DIM, DIM, 0,
                                            (size_t)HID*DIM, (size_t)H2*DIM);

        // ---- attention ----
        // fuse previous layer's MoE residual (yb) into this rmsnorm (l>0)
        rmsnorm_pack<<<SEQ, 256>>>(h, (l > 0) ? yb : nullptr,
                                   attn_norm_w + (size_t)l*DIM, nullptr, xnp_h, xnp_l);
        gemm_bf16p<<<dim3(DIM/128, SEQ/128, 3), 256, SMEM_BYTES>>>(
            xnp_h, xnp_l, wqkv_h, wqkv_l, (size_t)D2*DIM,
            qkv, DIM, nullptr, SEQ, DIM, D2, QKVS,
            nullptr, nullptr, nullptr, nullptr);
        rope_apply_kernel<<<SEQ, 512>>>(qkv, cosb, sinb);
        attn_kernel<<<dim3(SEQ/AQ, NH), 256>>>(qkv, op_h, op_l);
        gemm_bf16p<<<dim3(DIM/128, SEQ/128, 1), 256, SMEM_BYTES>>>(
            op_h, op_l, wop_h, wop_l, 0,
            h, 0, h, SEQ, DIM, D2, DIM,
            nullptr, nullptr, nullptr, nullptr);

        // ---- MoE ----
        rmsnorm_pack<<<SEQ, 256>>>(h, nullptr, ffn_norm_w + (size_t)l*DIM, xn, xnp_h, xnp_l);
        zero_cnt_kernel<<<1, 32>>>(cnt);
        router_kernel<<<SEQ, 256>>>(xn, router_w + (size_t)l*DIM*NEXP, cnt, sc, wt);
        finalize_router<<<1, 256>>>(cnt, offp, sc, wt, scf, wtf);

        // fused w1|w3 GEMM: N = 2816 combined
        gemm_bf16p<<<dim3(HID2/128, SEQ/128, NEXP), 256, SMEM_BYTES>>>(
            xnp_h, xnp_l, w13_h, w13_l, (size_t)D2*HID2,
            gu, 0, nullptr, SEQ, HID2, D2, HID2,
            sc, nullptr, cnt, offp);
        act_pack<<<dim3((H2 + 255)/256, 2*SEQ), 256>>>(gu, wtf, gbp_h, gbp_l);
        gemm_bf16p<<<dim3(DIM/128, SEQ/128, NEXP), 256, SMEM_BYTES>>>(
            gbp_h, gbp_l, w2p_h, w2p_l, (size_t)H2*DIM,
            yb, 0, nullptr, SEQ, DIM, H2, DIM,
            nullptr, scf, cnt, offp);
        // residual fused into next rmsnorm (or final below)
    }

    rmsnorm_pack_f16<<<SEQ, 256>>>(h, yb, final_norm_w, xnp_h);
    gemm_f16v<<<dim3(VOCAB/128, SEQ/128, 1), 256, V_BYTES>>>(
        xnp_h, wout16, out, SEQ, VOCAB, D2);

    (void)in_sizes; (void)n_in; (void)out_size;
}